// round 7
// baseline (speedup 1.0000x reference)
#include <cuda_runtime.h>
#include <cstdint>

// ---------------- problem constants ----------------
#define NNODES 100000
#define NEDGES 800000
#define NGRAPH 64
#define SCAN_CHUNK 1024
#define SCAN_NB ((NNODES + SCAN_CHUNK - 1) / SCAN_CHUNK)   // 98

// ---------------- scratch (static device globals; no allocation) ----------------
__device__ float4 g_bufA4[(size_t)NNODES * 32];   // 51.2 MB  (GEMM output h)
__device__ float4 g_bufB4[(size_t)NNODES * 32];   // 51.2 MB  (agg output / GEMM2 input)
__device__ float  g_dinv[NNODES];
__device__ int    g_cnti[NNODES];
__device__ int    g_off[NNODES + 1];
__device__ int    g_cursor[NNODES];
__device__ int    g_elist[NEDGES];
__device__ int    g_bsum[SCAN_NB];
__device__ int    g_bpre[SCAN_NB];
__device__ float  g_pool[NGRAPH * 128];
__device__ float  g_gcnt[NGRAPH];
// W fragments, pre-split tf32 hi/lo, pre-swizzled to m16n8k8 B-fragment order:
// idx = (kstep*16 + ntile)*32 + lane ; .x = b0 (k=ks*8+lane%4), .y = b1 (k+4)
__device__ uint2  g_wfh[8192];   // 64 KB
__device__ uint2  g_wfl[8192];   // 64 KB

// ---------------- tf32 helpers ----------------
__device__ __forceinline__ uint32_t f2tf32(float f) {
    uint32_t r;
    asm("cvt.rna.tf32.f32 %0, %1;" : "=r"(r) : "f"(f));
    return r;
}

#define MMA_TF32(d, a, b) \
    asm volatile("mma.sync.aligned.m16n8k8.row.col.f32.tf32.tf32.f32 " \
        "{%0,%1,%2,%3}, {%4,%5,%6,%7}, {%8,%9}, {%0,%1,%2,%3};" \
        : "+f"((d)[0]), "+f"((d)[1]), "+f"((d)[2]), "+f"((d)[3]) \
        : "r"((a)[0]), "r"((a)[1]), "r"((a)[2]), "r"((a)[3]), \
          "r"((b).x), "r"((b).y))

// ---------------- W split-convert into fragment order ----------------
__global__ void wconv_kernel(const float* __restrict__ W) {
    int i = blockIdx.x * blockDim.x + threadIdx.x;
    if (i >= 8192) return;
    int lane = i & 31, ntg = (i >> 5) & 15, ks = i >> 9;
    int n = ntg * 8 + (lane >> 2);
    int k = ks * 8 + (lane & 3);
    float b0 = W[(size_t)k * 128 + n];
    float b1 = W[(size_t)(k + 4) * 128 + n];
    uint32_t h0 = f2tf32(b0), h1 = f2tf32(b1);
    float l0 = b0 - __uint_as_float(h0);
    float l1 = b1 - __uint_as_float(h1);
    g_wfh[i] = make_uint2(h0, h1);
    g_wfl[i] = make_uint2(f2tf32(l0), f2tf32(l1));
}

// ---------------- tensor-core GEMM (mma.sync, 3xTF32) ----------------
// g_bufA = A[M,128] @ W[128,128]. 256 threads, warp grid 2(m) x 4(n),
// warp tile 64x32, m16n8k8 fragments. A split to tf32 hi/lo in smem.
#define A_LDA 132   // padded row stride (u32 units) -> conflict-free frag LDS
__global__ __launch_bounds__(256)
void tc_gemm_kernel(const float* __restrict__ Aext, int useExt, int M) {
    extern __shared__ uint32_t sm[];
    uint32_t* Ash = sm;                 // [128][132]
    uint32_t* Asl = sm + 128 * A_LDA;   // [128][132]
    const float* __restrict__ A = useExt ? Aext : reinterpret_cast<const float*>(g_bufB4);
    const int tid = threadIdx.x, lane = tid & 31, wid = tid >> 5;
    const int block_row = blockIdx.x * 128;

    // load A tile, split to tf32 hi/lo, store padded
    for (int i = tid; i < 4096; i += 256) {
        int r = i >> 5, c = (i & 31) * 4;
        float4 v = make_float4(0.f, 0.f, 0.f, 0.f);
        if (block_row + r < M)
            v = *reinterpret_cast<const float4*>(A + (size_t)(block_row + r) * 128 + c);
        uint32_t h0 = f2tf32(v.x), h1 = f2tf32(v.y), h2 = f2tf32(v.z), h3 = f2tf32(v.w);
        uint32_t l0 = f2tf32(v.x - __uint_as_float(h0));
        uint32_t l1 = f2tf32(v.y - __uint_as_float(h1));
        uint32_t l2 = f2tf32(v.z - __uint_as_float(h2));
        uint32_t l3 = f2tf32(v.w - __uint_as_float(h3));
        *reinterpret_cast<uint4*>(&Ash[r * A_LDA + c]) = make_uint4(h0, h1, h2, h3);
        *reinterpret_cast<uint4*>(&Asl[r * A_LDA + c]) = make_uint4(l0, l1, l2, l3);
    }
    __syncthreads();

    const int wm = (wid >> 2) * 64;     // warp m base (0 or 64)
    const int wn = (wid & 3) * 32;      // warp n base
    const int g  = lane >> 2;           // group id 0..7
    const int t  = lane & 3;            // thread-in-group

    float acc[4][4][4];
#pragma unroll
    for (int a = 0; a < 4; a++)
#pragma unroll
        for (int b = 0; b < 4; b++)
#pragma unroll
            for (int c = 0; c < 4; c++) acc[a][b][c] = 0.f;

    for (int ks = 0; ks < 16; ks++) {
        const int k0 = ks * 8;
        uint32_t ah[4][4], al[4][4];
#pragma unroll
        for (int mt = 0; mt < 4; mt++) {
            const int r0 = (wm + mt * 16 + g) * A_LDA;
            ah[mt][0] = Ash[r0 + k0 + t];
            ah[mt][1] = Ash[r0 + 8 * A_LDA + k0 + t];
            ah[mt][2] = Ash[r0 + k0 + t + 4];
            ah[mt][3] = Ash[r0 + 8 * A_LDA + k0 + t + 4];
            al[mt][0] = Asl[r0 + k0 + t];
            al[mt][1] = Asl[r0 + 8 * A_LDA + k0 + t];
            al[mt][2] = Asl[r0 + k0 + t + 4];
            al[mt][3] = Asl[r0 + 8 * A_LDA + k0 + t + 4];
        }
        uint2 bh[4], bl[4];
#pragma unroll
        for (int nt = 0; nt < 4; nt++) {
            const int idx = (ks * 16 + (wn >> 3) + nt) * 32 + lane;
            bh[nt] = g_wfh[idx];
            bl[nt] = g_wfl[idx];
        }
#pragma unroll
        for (int mt = 0; mt < 4; mt++)
#pragma unroll
            for (int nt = 0; nt < 4; nt++) {
                MMA_TF32(acc[mt][nt], ah[mt], bh[nt]);   // hi*hi
                MMA_TF32(acc[mt][nt], ah[mt], bl[nt]);   // hi*lo
                MMA_TF32(acc[mt][nt], al[mt], bh[nt]);   // lo*hi
            }
    }

    // epilogue: c0/c1 -> (row, 2t..2t+1); c2/c3 -> (row+8, same)
    float* C = reinterpret_cast<float*>(g_bufA4);
#pragma unroll
    for (int mt = 0; mt < 4; mt++) {
        const int row0 = block_row + wm + mt * 16 + g;
#pragma unroll
        for (int nt = 0; nt < 4; nt++) {
            const int col = wn + nt * 8 + t * 2;
            if (row0 < M)
                *reinterpret_cast<float2*>(C + (size_t)row0 * 128 + col) =
                    make_float2(acc[mt][nt][0], acc[mt][nt][1]);
            if (row0 + 8 < M)
                *reinterpret_cast<float2*>(C + (size_t)(row0 + 8) * 128 + col) =
                    make_float2(acc[mt][nt][2], acc[mt][nt][3]);
        }
    }
}
#define GEMM_SMEM (2 * 128 * A_LDA * 4)   // 135168 bytes

// ================= CSR build / aggregation / pool / fc (round-5 proven) =================
__global__ void zero_misc_kernel() {
    int i = blockIdx.x * blockDim.x + threadIdx.x;
    int stride = gridDim.x * blockDim.x;
    for (int k = i; k < NNODES; k += stride) g_cnti[k] = 0;
    if (i < NGRAPH * 128) g_pool[i] = 0.f;
    if (i < NGRAPH) g_gcnt[i] = 0.f;
}

__global__ void count_kernel(const int* __restrict__ dst, int E) {
    int e = blockIdx.x * blockDim.x + threadIdx.x;
    if (e >= E) return;
    atomicAdd(&g_cnti[dst[e]], 1);
}

__global__ __launch_bounds__(256)
void scanA_kernel() {
    __shared__ int ssum[8];
    const int tid = threadIdx.x;
    const int base = blockIdx.x * SCAN_CHUNK + tid * 4;
    int s = 0;
#pragma unroll
    for (int j = 0; j < 4; j++) {
        int idx = base + j;
        if (idx < NNODES) s += g_cnti[idx];
    }
#pragma unroll
    for (int o = 16; o > 0; o >>= 1) s += __shfl_down_sync(0xffffffffu, s, o);
    if ((tid & 31) == 0) ssum[tid >> 5] = s;
    __syncthreads();
    if (tid == 0) {
        int tt = 0;
#pragma unroll
        for (int w = 0; w < 8; w++) tt += ssum[w];
        g_bsum[blockIdx.x] = tt;
    }
}

__global__ __launch_bounds__(128)
void scanB_kernel() {
    __shared__ int sh[128];
    const int t = threadIdx.x;
    int v = (t < SCAN_NB) ? g_bsum[t] : 0;
    sh[t] = v;
    __syncthreads();
    for (int o = 1; o < 128; o <<= 1) {
        int add = (t >= o) ? sh[t - o] : 0;
        __syncthreads();
        sh[t] += add;
        __syncthreads();
    }
    if (t < SCAN_NB) g_bpre[t] = sh[t] - v;
    if (t == SCAN_NB - 1) g_off[NNODES] = sh[t];
}

__global__ __launch_bounds__(256)
void scanC_kernel() {
    __shared__ int warpsum[8];
    const int tid = threadIdx.x;
    const int lane = tid & 31;
    const int warp = tid >> 5;
    const int base = blockIdx.x * SCAN_CHUNK + tid * 4;

    int v[4];
    int t = 0;
#pragma unroll
    for (int j = 0; j < 4; j++) {
        int idx = base + j;
        v[j] = (idx < NNODES) ? g_cnti[idx] : 0;
        t += v[j];
    }
    int incl = t;
#pragma unroll
    for (int o = 1; o < 32; o <<= 1) {
        int n = __shfl_up_sync(0xffffffffu, incl, o);
        if (lane >= o) incl += n;
    }
    if (lane == 31) warpsum[warp] = incl;
    __syncthreads();
    if (tid == 0) {
        int run = 0;
#pragma unroll
        for (int w = 0; w < 8; w++) { int x = warpsum[w]; warpsum[w] = run; run += x; }
    }
    __syncthreads();
    int run = g_bpre[blockIdx.x] + warpsum[warp] + (incl - t);
#pragma unroll
    for (int j = 0; j < 4; j++) {
        int idx = base + j;
        if (idx < NNODES) {
            g_off[idx] = run;
            g_cursor[idx] = run;
            g_dinv[idx] = rsqrtf((float)v[j] + 1.0f);
            run += v[j];
        }
    }
}

__global__ void fill_kernel(const int* __restrict__ src,
                            const int* __restrict__ dst, int E) {
    int e = blockIdx.x * blockDim.x + threadIdx.x;
    if (e >= E) return;
    int d = dst[e];
    int pos = atomicAdd(&g_cursor[d], 1);
    g_elist[pos] = src[e];
}

__global__ __launch_bounds__(256)
void agg_gather_kernel(const float* __restrict__ bias) {
    const int node = (blockIdx.x * blockDim.x + threadIdx.x) >> 5;
    const int lane = threadIdx.x & 31;
    if (node >= NNODES) return;

    const float4* __restrict__ h4 = g_bufA4;
    const float dd = g_dinv[node];

    float4 hv = h4[(size_t)node * 32 + lane];
    const float ws = dd * dd;
    float4 acc;
    acc.x = ws * hv.x; acc.y = ws * hv.y; acc.z = ws * hv.z; acc.w = ws * hv.w;

    const int beg = g_off[node];
    const int end = g_off[node + 1];
    int i = beg;
    for (; i + 3 < end; i += 4) {
        int   s[4];
        float w[4];
        float4 v[4];
#pragma unroll
        for (int u = 0; u < 4; u++) s[u] = g_elist[i + u];
#pragma unroll
        for (int u = 0; u < 4; u++) w[u] = dd * g_dinv[s[u]];
#pragma unroll
        for (int u = 0; u < 4; u++) v[u] = h4[(size_t)s[u] * 32 + lane];
#pragma unroll
        for (int u = 0; u < 4; u++) {
            acc.x = fmaf(w[u], v[u].x, acc.x);
            acc.y = fmaf(w[u], v[u].y, acc.y);
            acc.z = fmaf(w[u], v[u].z, acc.z);
            acc.w = fmaf(w[u], v[u].w, acc.w);
        }
    }
    for (; i < end; i++) {
        const int s = g_elist[i];
        const float w = dd * g_dinv[s];
        const float4 v = h4[(size_t)s * 32 + lane];
        acc.x = fmaf(w, v.x, acc.x);
        acc.y = fmaf(w, v.y, acc.y);
        acc.z = fmaf(w, v.z, acc.z);
        acc.w = fmaf(w, v.w, acc.w);
    }

    const float4 bv = reinterpret_cast<const float4*>(bias)[lane];
    acc.x = fmaxf(acc.x + bv.x, 0.f);
    acc.y = fmaxf(acc.y + bv.y, 0.f);
    acc.z = fmaxf(acc.z + bv.z, 0.f);
    acc.w = fmaxf(acc.w + bv.w, 0.f);
    g_bufB4[(size_t)node * 32 + lane] = acc;
}

#define POOL_NODES_PER_BLOCK 128
__global__ __launch_bounds__(128)
void pool_kernel(const int* __restrict__ batch, int N) {
    const int n0 = blockIdx.x * POOL_NODES_PER_BLOCK;
    const int n1 = min(n0 + POOL_NODES_PER_BLOCK, N);
    const int d = threadIdx.x;
    const float* __restrict__ h = reinterpret_cast<const float*>(g_bufB4);

    float acc = 0.f, c = 0.f;
    int curg = -1;
    for (int n = n0; n < n1; n++) {
        const int g = batch[n];
        if (g != curg) {
            if (curg >= 0) {
                atomicAdd(&g_pool[curg * 128 + d], acc);
                if (d == 0) atomicAdd(&g_gcnt[curg], c);
            }
            curg = g; acc = 0.f; c = 0.f;
        }
        acc += h[(size_t)n * 128 + d];
        c += 1.f;
    }
    if (curg >= 0) {
        atomicAdd(&g_pool[curg * 128 + d], acc);
        if (d == 0) atomicAdd(&g_gcnt[curg], c);
    }
}

__global__ __launch_bounds__(128)
void fc_kernel(const float* __restrict__ W, const float* __restrict__ b,
               float* __restrict__ out) {
    __shared__ float row[128];
    const int g = blockIdx.x;
    const int j = threadIdx.x;
    const float inv = 1.0f / fmaxf(g_gcnt[g], 1.0f);
    row[j] = g_pool[g * 128 + j] * inv;
    __syncthreads();
    float acc = b[j];
#pragma unroll
    for (int k = 0; k < 128; k++)
        acc = fmaf(row[k], W[k * 128 + j], acc);
    out[g * 128 + j] = acc;
}

// ---------------- launch ----------------
extern "C" void kernel_launch(void* const* d_in, const int* in_sizes, int n_in,
                              void* d_out, int out_size) {
    const float* x   = (const float*)d_in[0];
    const int*   ei  = (const int*)d_in[1];    // int32 (JAX x64 disabled)
    const int*   bat = (const int*)d_in[2];
    const float* W1  = (const float*)d_in[3];
    const float* b1  = (const float*)d_in[4];
    const float* W2  = (const float*)d_in[5];
    const float* b2  = (const float*)d_in[6];
    const float* Wfc = (const float*)d_in[7];
    const float* bfc = (const float*)d_in[8];
    float*       out = (float*)d_out;

    const int N = in_sizes[2];
    const int E = in_sizes[1] / 2;
    const int* src = ei;
    const int* dst = ei + E;

    cudaFuncSetAttribute(tc_gemm_kernel, cudaFuncAttributeMaxDynamicSharedMemorySize, GEMM_SMEM);

    const int gemm_blocks = (N + 127) / 128;          // 782
    const int agg_blocks  = (N * 32 + 255) / 256;     // warp per node

    zero_misc_kernel<<<1184, 256>>>();                                  // 1
    count_kernel<<<(E + 255) / 256, 256>>>(dst, E);                     // 2
    wconv_kernel<<<32, 256>>>(W1);                                      // 3
    tc_gemm_kernel<<<gemm_blocks, 256, GEMM_SMEM>>>(x, 1, N);           // 4 <- profiled
    scanA_kernel<<<SCAN_NB, 256>>>();                                   // 5
    scanB_kernel<<<1, 128>>>();                                         // 6
    scanC_kernel<<<SCAN_NB, 256>>>();                                   // 7
    fill_kernel<<<(E + 255) / 256, 256>>>(src, dst, E);                 // 8
    agg_gather_kernel<<<agg_blocks, 256>>>(b1);                         // 9
    wconv_kernel<<<32, 256>>>(W2);                                      // 10
    tc_gemm_kernel<<<gemm_blocks, 256, GEMM_SMEM>>>(nullptr, 0, N);     // 11
    agg_gather_kernel<<<agg_blocks, 256>>>(b2);                         // 12
    pool_kernel<<<(N + POOL_NODES_PER_BLOCK - 1) / POOL_NODES_PER_BLOCK, 128>>>(bat, N); // 13
    fc_kernel<<<NGRAPH, 128>>>(Wfc, bfc, out);                          // 14
}

// round 8
// speedup vs baseline: 1.2608x; 1.2608x over previous
#include <cuda_runtime.h>
#include <cstdint>

// ---------------- problem constants ----------------
#define NNODES 100000
#define NEDGES 800000
#define NGRAPH 64
#define SCAN_CHUNK 1024
#define SCAN_NB ((NNODES + SCAN_CHUNK - 1) / SCAN_CHUNK)   // 98

// ---------------- scratch (static device globals; no allocation) ----------------
__device__ float4 g_bufA4[(size_t)NNODES * 32];   // 51.2 MB  (GEMM output h)
__device__ float4 g_bufB4[(size_t)NNODES * 32];   // 51.2 MB  (agg output / GEMM2 input)
__device__ float  g_dinv[NNODES];
__device__ int    g_cnti[NNODES];
__device__ int    g_off[NNODES + 1];
__device__ int    g_cursor[NNODES];
__device__ int    g_elist[NEDGES];
__device__ int    g_bsum[SCAN_NB];
__device__ int    g_bpre[SCAN_NB];
__device__ float  g_pool[NGRAPH * 128];
__device__ float  g_gcnt[NGRAPH];
// W fragments, pre-split tf32 hi/lo, pre-swizzled to m16n8k8 B-fragment order:
// idx = (kstep*16 + ntile)*32 + lane ; .x = b0 (k=ks*8+lane%4), .y = b1 (k+4)
__device__ uint2  g_wfh[8192];   // 64 KB
__device__ uint2  g_wfl[8192];   // 64 KB

// ---------------- tf32 helpers ----------------
__device__ __forceinline__ uint32_t f2tf32(float f) {
    uint32_t r;
    asm("cvt.rna.tf32.f32 %0, %1;" : "=r"(r) : "f"(f));
    return r;
}

#define MMA_TF32(d, a, b) \
    asm volatile("mma.sync.aligned.m16n8k8.row.col.f32.tf32.tf32.f32 " \
        "{%0,%1,%2,%3}, {%4,%5,%6,%7}, {%8,%9}, {%0,%1,%2,%3};" \
        : "+f"((d)[0]), "+f"((d)[1]), "+f"((d)[2]), "+f"((d)[3]) \
        : "r"((a)[0]), "r"((a)[1]), "r"((a)[2]), "r"((a)[3]), \
          "r"((b).x), "r"((b).y))

// ---------------- W split-convert into fragment order ----------------
__global__ void wconv_kernel(const float* __restrict__ W) {
    int i = blockIdx.x * blockDim.x + threadIdx.x;
    if (i >= 8192) return;
    int lane = i & 31, ntg = (i >> 5) & 15, ks = i >> 9;
    int n = ntg * 8 + (lane >> 2);
    int k = ks * 8 + (lane & 3);
    float b0 = W[(size_t)k * 128 + n];
    float b1 = W[(size_t)(k + 4) * 128 + n];
    uint32_t h0 = f2tf32(b0), h1 = f2tf32(b1);
    float l0 = b0 - __uint_as_float(h0);
    float l1 = b1 - __uint_as_float(h1);
    g_wfh[i] = make_uint2(h0, h1);
    g_wfl[i] = make_uint2(f2tf32(l0), f2tf32(l1));
}

// ---------------- tensor-core GEMM (mma.sync, 3xTF32) ----------------
// g_bufA = A[M,128] @ W[128,128]. CTA tile 64(m) x 128(n), 128 threads,
// 4 warps in 1x4 n-grid, warp tile 64x32, m16n8k8 fragments.
// smem: A tile split tf32 hi/lo, 64x132 padded each -> 67.6 KB -> 3 CTAs/SM.
#define A_LDA 132
#define GEMM_BM 64
__global__ __launch_bounds__(128)
void tc_gemm_kernel(const float* __restrict__ Aext, int useExt, int M) {
    extern __shared__ uint32_t sm[];
    uint32_t* Ash = sm;                      // [64][132]
    uint32_t* Asl = sm + GEMM_BM * A_LDA;    // [64][132]
    const float* __restrict__ A = useExt ? Aext : reinterpret_cast<const float*>(g_bufB4);
    const int tid = threadIdx.x, lane = tid & 31, wid = tid >> 5;
    const int block_row = blockIdx.x * GEMM_BM;

    // load A tile, split to tf32 hi/lo, store padded
    for (int i = tid; i < GEMM_BM * 32; i += 128) {
        int r = i >> 5, c = (i & 31) * 4;
        float4 v = make_float4(0.f, 0.f, 0.f, 0.f);
        if (block_row + r < M)
            v = *reinterpret_cast<const float4*>(A + (size_t)(block_row + r) * 128 + c);
        uint32_t h0 = f2tf32(v.x), h1 = f2tf32(v.y), h2 = f2tf32(v.z), h3 = f2tf32(v.w);
        uint32_t l0 = f2tf32(v.x - __uint_as_float(h0));
        uint32_t l1 = f2tf32(v.y - __uint_as_float(h1));
        uint32_t l2 = f2tf32(v.z - __uint_as_float(h2));
        uint32_t l3 = f2tf32(v.w - __uint_as_float(h3));
        *reinterpret_cast<uint4*>(&Ash[r * A_LDA + c]) = make_uint4(h0, h1, h2, h3);
        *reinterpret_cast<uint4*>(&Asl[r * A_LDA + c]) = make_uint4(l0, l1, l2, l3);
    }
    __syncthreads();

    const int wn = wid * 32;            // warp n base
    const int g  = lane >> 2;           // group id 0..7
    const int t  = lane & 3;            // thread-in-group

    float acc[4][4][4];
#pragma unroll
    for (int a = 0; a < 4; a++)
#pragma unroll
        for (int b = 0; b < 4; b++)
#pragma unroll
            for (int c = 0; c < 4; c++) acc[a][b][c] = 0.f;

#pragma unroll 2
    for (int ks = 0; ks < 16; ks++) {
        const int k0 = ks * 8;
        uint2 bh[4], bl[4];
#pragma unroll
        for (int nt = 0; nt < 4; nt++) {
            const int idx = (ks * 16 + (wn >> 3) + nt) * 32 + lane;
            bh[nt] = g_wfh[idx];
            bl[nt] = g_wfl[idx];
        }
        uint32_t ah[4][4], al[4][4];
#pragma unroll
        for (int mt = 0; mt < 4; mt++) {
            const int r0 = (mt * 16 + g) * A_LDA;
            ah[mt][0] = Ash[r0 + k0 + t];
            ah[mt][1] = Ash[r0 + 8 * A_LDA + k0 + t];
            ah[mt][2] = Ash[r0 + k0 + t + 4];
            ah[mt][3] = Ash[r0 + 8 * A_LDA + k0 + t + 4];
            al[mt][0] = Asl[r0 + k0 + t];
            al[mt][1] = Asl[r0 + 8 * A_LDA + k0 + t];
            al[mt][2] = Asl[r0 + k0 + t + 4];
            al[mt][3] = Asl[r0 + 8 * A_LDA + k0 + t + 4];
        }
#pragma unroll
        for (int mt = 0; mt < 4; mt++)
#pragma unroll
            for (int nt = 0; nt < 4; nt++) {
                MMA_TF32(acc[mt][nt], ah[mt], bh[nt]);   // hi*hi
                MMA_TF32(acc[mt][nt], ah[mt], bl[nt]);   // hi*lo
                MMA_TF32(acc[mt][nt], al[mt], bh[nt]);   // lo*hi
            }
    }

    // epilogue: c0/c1 -> (row, 2t..2t+1); c2/c3 -> (row+8, same)
    float* C = reinterpret_cast<float*>(g_bufA4);
#pragma unroll
    for (int mt = 0; mt < 4; mt++) {
        const int row0 = block_row + mt * 16 + g;
#pragma unroll
        for (int nt = 0; nt < 4; nt++) {
            const int col = wn + nt * 8 + t * 2;
            if (row0 < M)
                *reinterpret_cast<float2*>(C + (size_t)row0 * 128 + col) =
                    make_float2(acc[mt][nt][0], acc[mt][nt][1]);
            if (row0 + 8 < M)
                *reinterpret_cast<float2*>(C + (size_t)(row0 + 8) * 128 + col) =
                    make_float2(acc[mt][nt][2], acc[mt][nt][3]);
        }
    }
}
#define GEMM_SMEM (2 * GEMM_BM * A_LDA * 4)   // 67584 bytes -> 3 CTAs/SM

// ================= CSR build / aggregation / pool / fc (round-5 proven) =================
__global__ void zero_misc_kernel() {
    int i = blockIdx.x * blockDim.x + threadIdx.x;
    int stride = gridDim.x * blockDim.x;
    for (int k = i; k < NNODES; k += stride) g_cnti[k] = 0;
    if (i < NGRAPH * 128) g_pool[i] = 0.f;
    if (i < NGRAPH) g_gcnt[i] = 0.f;
}

__global__ void count_kernel(const int* __restrict__ dst, int E) {
    int e = blockIdx.x * blockDim.x + threadIdx.x;
    if (e >= E) return;
    atomicAdd(&g_cnti[dst[e]], 1);
}

__global__ __launch_bounds__(256)
void scanA_kernel() {
    __shared__ int ssum[8];
    const int tid = threadIdx.x;
    const int base = blockIdx.x * SCAN_CHUNK + tid * 4;
    int s = 0;
#pragma unroll
    for (int j = 0; j < 4; j++) {
        int idx = base + j;
        if (idx < NNODES) s += g_cnti[idx];
    }
#pragma unroll
    for (int o = 16; o > 0; o >>= 1) s += __shfl_down_sync(0xffffffffu, s, o);
    if ((tid & 31) == 0) ssum[tid >> 5] = s;
    __syncthreads();
    if (tid == 0) {
        int tt = 0;
#pragma unroll
        for (int w = 0; w < 8; w++) tt += ssum[w];
        g_bsum[blockIdx.x] = tt;
    }
}

__global__ __launch_bounds__(128)
void scanB_kernel() {
    __shared__ int sh[128];
    const int t = threadIdx.x;
    int v = (t < SCAN_NB) ? g_bsum[t] : 0;
    sh[t] = v;
    __syncthreads();
    for (int o = 1; o < 128; o <<= 1) {
        int add = (t >= o) ? sh[t - o] : 0;
        __syncthreads();
        sh[t] += add;
        __syncthreads();
    }
    if (t < SCAN_NB) g_bpre[t] = sh[t] - v;
    if (t == SCAN_NB - 1) g_off[NNODES] = sh[t];
}

__global__ __launch_bounds__(256)
void scanC_kernel() {
    __shared__ int warpsum[8];
    const int tid = threadIdx.x;
    const int lane = tid & 31;
    const int warp = tid >> 5;
    const int base = blockIdx.x * SCAN_CHUNK + tid * 4;

    int v[4];
    int t = 0;
#pragma unroll
    for (int j = 0; j < 4; j++) {
        int idx = base + j;
        v[j] = (idx < NNODES) ? g_cnti[idx] : 0;
        t += v[j];
    }
    int incl = t;
#pragma unroll
    for (int o = 1; o < 32; o <<= 1) {
        int n = __shfl_up_sync(0xffffffffu, incl, o);
        if (lane >= o) incl += n;
    }
    if (lane == 31) warpsum[warp] = incl;
    __syncthreads();
    if (tid == 0) {
        int run = 0;
#pragma unroll
        for (int w = 0; w < 8; w++) { int x = warpsum[w]; warpsum[w] = run; run += x; }
    }
    __syncthreads();
    int run = g_bpre[blockIdx.x] + warpsum[warp] + (incl - t);
#pragma unroll
    for (int j = 0; j < 4; j++) {
        int idx = base + j;
        if (idx < NNODES) {
            g_off[idx] = run;
            g_cursor[idx] = run;
            g_dinv[idx] = rsqrtf((float)v[j] + 1.0f);
            run += v[j];
        }
    }
}

__global__ void fill_kernel(const int* __restrict__ src,
                            const int* __restrict__ dst, int E) {
    int e = blockIdx.x * blockDim.x + threadIdx.x;
    if (e >= E) return;
    int d = dst[e];
    int pos = atomicAdd(&g_cursor[d], 1);
    g_elist[pos] = src[e];
}

__global__ __launch_bounds__(256)
void agg_gather_kernel(const float* __restrict__ bias) {
    const int node = (blockIdx.x * blockDim.x + threadIdx.x) >> 5;
    const int lane = threadIdx.x & 31;
    if (node >= NNODES) return;

    const float4* __restrict__ h4 = g_bufA4;
    const float dd = g_dinv[node];

    float4 hv = h4[(size_t)node * 32 + lane];
    const float ws = dd * dd;
    float4 acc;
    acc.x = ws * hv.x; acc.y = ws * hv.y; acc.z = ws * hv.z; acc.w = ws * hv.w;

    const int beg = g_off[node];
    const int end = g_off[node + 1];
    int i = beg;
    for (; i + 3 < end; i += 4) {
        int   s[4];
        float w[4];
        float4 v[4];
#pragma unroll
        for (int u = 0; u < 4; u++) s[u] = g_elist[i + u];
#pragma unroll
        for (int u = 0; u < 4; u++) w[u] = dd * g_dinv[s[u]];
#pragma unroll
        for (int u = 0; u < 4; u++) v[u] = h4[(size_t)s[u] * 32 + lane];
#pragma unroll
        for (int u = 0; u < 4; u++) {
            acc.x = fmaf(w[u], v[u].x, acc.x);
            acc.y = fmaf(w[u], v[u].y, acc.y);
            acc.z = fmaf(w[u], v[u].z, acc.z);
            acc.w = fmaf(w[u], v[u].w, acc.w);
        }
    }
    for (; i < end; i++) {
        const int s = g_elist[i];
        const float w = dd * g_dinv[s];
        const float4 v = h4[(size_t)s * 32 + lane];
        acc.x = fmaf(w, v.x, acc.x);
        acc.y = fmaf(w, v.y, acc.y);
        acc.z = fmaf(w, v.z, acc.z);
        acc.w = fmaf(w, v.w, acc.w);
    }

    const float4 bv = reinterpret_cast<const float4*>(bias)[lane];
    acc.x = fmaxf(acc.x + bv.x, 0.f);
    acc.y = fmaxf(acc.y + bv.y, 0.f);
    acc.z = fmaxf(acc.z + bv.z, 0.f);
    acc.w = fmaxf(acc.w + bv.w, 0.f);
    g_bufB4[(size_t)node * 32 + lane] = acc;
}

#define POOL_NODES_PER_BLOCK 128
__global__ __launch_bounds__(128)
void pool_kernel(const int* __restrict__ batch, int N) {
    const int n0 = blockIdx.x * POOL_NODES_PER_BLOCK;
    const int n1 = min(n0 + POOL_NODES_PER_BLOCK, N);
    const int d = threadIdx.x;
    const float* __restrict__ h = reinterpret_cast<const float*>(g_bufB4);

    float acc = 0.f, c = 0.f;
    int curg = -1;
    for (int n = n0; n < n1; n++) {
        const int g = batch[n];
        if (g != curg) {
            if (curg >= 0) {
                atomicAdd(&g_pool[curg * 128 + d], acc);
                if (d == 0) atomicAdd(&g_gcnt[curg], c);
            }
            curg = g; acc = 0.f; c = 0.f;
        }
        acc += h[(size_t)n * 128 + d];
        c += 1.f;
    }
    if (curg >= 0) {
        atomicAdd(&g_pool[curg * 128 + d], acc);
        if (d == 0) atomicAdd(&g_gcnt[curg], c);
    }
}

__global__ __launch_bounds__(128)
void fc_kernel(const float* __restrict__ W, const float* __restrict__ b,
               float* __restrict__ out) {
    __shared__ float row[128];
    const int g = blockIdx.x;
    const int j = threadIdx.x;
    const float inv = 1.0f / fmaxf(g_gcnt[g], 1.0f);
    row[j] = g_pool[g * 128 + j] * inv;
    __syncthreads();
    float acc = b[j];
#pragma unroll
    for (int k = 0; k < 128; k++)
        acc = fmaf(row[k], W[k * 128 + j], acc);
    out[g * 128 + j] = acc;
}

// ---------------- launch ----------------
extern "C" void kernel_launch(void* const* d_in, const int* in_sizes, int n_in,
                              void* d_out, int out_size) {
    const float* x   = (const float*)d_in[0];
    const int*   ei  = (const int*)d_in[1];    // int32 (JAX x64 disabled)
    const int*   bat = (const int*)d_in[2];
    const float* W1  = (const float*)d_in[3];
    const float* b1  = (const float*)d_in[4];
    const float* W2  = (const float*)d_in[5];
    const float* b2  = (const float*)d_in[6];
    const float* Wfc = (const float*)d_in[7];
    const float* bfc = (const float*)d_in[8];
    float*       out = (float*)d_out;

    const int N = in_sizes[2];
    const int E = in_sizes[1] / 2;
    const int* src = ei;
    const int* dst = ei + E;

    cudaFuncSetAttribute(tc_gemm_kernel, cudaFuncAttributeMaxDynamicSharedMemorySize, GEMM_SMEM);

    const int gemm_blocks = (N + GEMM_BM - 1) / GEMM_BM;   // 1563
    const int agg_blocks  = (N * 32 + 255) / 256;          // warp per node

    zero_misc_kernel<<<1184, 256>>>();                                  // 1
    count_kernel<<<(E + 255) / 256, 256>>>(dst, E);                     // 2
    wconv_kernel<<<32, 256>>>(W1);                                      // 3
    tc_gemm_kernel<<<gemm_blocks, 128, GEMM_SMEM>>>(x, 1, N);           // 4 <- profiled
    scanA_kernel<<<SCAN_NB, 256>>>();                                   // 5
    scanB_kernel<<<1, 128>>>();                                         // 6
    scanC_kernel<<<SCAN_NB, 256>>>();                                   // 7
    fill_kernel<<<(E + 255) / 256, 256>>>(src, dst, E);                 // 8
    agg_gather_kernel<<<agg_blocks, 256>>>(b1);                         // 9
    wconv_kernel<<<32, 256>>>(W2);                                      // 10
    tc_gemm_kernel<<<gemm_blocks, 128, GEMM_SMEM>>>(nullptr, 0, N);     // 11
    agg_gather_kernel<<<agg_blocks, 256>>>(b2);                         // 12
    pool_kernel<<<(N + POOL_NODES_PER_BLOCK - 1) / POOL_NODES_PER_BLOCK, 128>>>(bat, N); // 13
    fc_kernel<<<NGRAPH, 128>>>(Wfc, bfc, out);                          // 14
}

// round 9
// speedup vs baseline: 1.3601x; 1.0788x over previous
#include <cuda_runtime.h>
#include <cstdint>

// ---------------- problem constants ----------------
#define NNODES 100000
#define NEDGES 800000
#define NGRAPH 64
#define SCAN_CHUNK 1024
#define SCAN_NB ((NNODES + SCAN_CHUNK - 1) / SCAN_CHUNK)   // 98

// ---------------- scratch (static device globals; no allocation) ----------------
__device__ float4 g_bufA4[(size_t)NNODES * 32];   // 51.2 MB  (GEMM output h)
__device__ float4 g_bufB4[(size_t)NNODES * 32];   // 51.2 MB  (agg output / GEMM2 input)
__device__ float  g_dinv[NNODES];
__device__ int    g_cnti[NNODES];
__device__ int    g_off[NNODES + 1];
__device__ int    g_cursor[NNODES];
__device__ int    g_elist[NEDGES];
__device__ int    g_bsum[SCAN_NB];
__device__ int    g_bpre[SCAN_NB];
__device__ float  g_pool[NGRAPH * 128];
__device__ float  g_gcnt[NGRAPH];
// W fragments, pre-split tf32 hi/lo, pre-swizzled to m16n8k8 B-fragment order:
// idx = (kstep*16 + ntile)*32 + lane ; .x = b0 (k=ks*8+lane%4), .y = b1 (k+4)
__device__ uint2  g_wfh[8192];   // 64 KB
__device__ uint2  g_wfl[8192];   // 64 KB

// ---------------- tf32 helpers ----------------
__device__ __forceinline__ uint32_t f2tf32(float f) {
    uint32_t r;
    asm("cvt.rna.tf32.f32 %0, %1;" : "=r"(r) : "f"(f));
    return r;
}

#define MMA_TF32(d, a, b) \
    asm volatile("mma.sync.aligned.m16n8k8.row.col.f32.tf32.tf32.f32 " \
        "{%0,%1,%2,%3}, {%4,%5,%6,%7}, {%8,%9}, {%0,%1,%2,%3};" \
        : "+f"((d)[0]), "+f"((d)[1]), "+f"((d)[2]), "+f"((d)[3]) \
        : "r"((a)[0]), "r"((a)[1]), "r"((a)[2]), "r"((a)[3]), \
          "r"((b).x), "r"((b).y))

// ---------------- W split-convert into fragment order ----------------
__global__ void wconv_kernel(const float* __restrict__ W) {
    int i = blockIdx.x * blockDim.x + threadIdx.x;
    if (i >= 8192) return;
    int lane = i & 31, ntg = (i >> 5) & 15, ks = i >> 9;
    int n = ntg * 8 + (lane >> 2);
    int k = ks * 8 + (lane & 3);
    float b0 = W[(size_t)k * 128 + n];
    float b1 = W[(size_t)(k + 4) * 128 + n];
    uint32_t h0 = f2tf32(b0), h1 = f2tf32(b1);
    float l0 = b0 - __uint_as_float(h0);
    float l1 = b1 - __uint_as_float(h1);
    g_wfh[i] = make_uint2(h0, h1);
    g_wfl[i] = make_uint2(f2tf32(l0), f2tf32(l1));
}

// ---------------- tensor-core GEMM (mma.sync, 3xTF32) ----------------
// g_bufA = A[M,128] @ W[128,128]. CTA tile 32(m) x 128(n), 128 threads,
// 4 warps in 1x4 n-grid, warp tile 32x32, m16n8k8 fragments.
// smem: A tile split tf32 hi/lo, 32x132 padded each -> 33.8 KB -> ~5 CTAs/SM.
#define A_LDA 132
#define GEMM_BM 32
__global__ __launch_bounds__(128)
void tc_gemm_kernel(const float* __restrict__ Aext, int useExt, int M) {
    extern __shared__ uint32_t sm[];
    uint32_t* Ash = sm;                      // [32][132]
    uint32_t* Asl = sm + GEMM_BM * A_LDA;    // [32][132]
    const float* __restrict__ A = useExt ? Aext : reinterpret_cast<const float*>(g_bufB4);
    const int tid = threadIdx.x, lane = tid & 31, wid = tid >> 5;
    const int block_row = blockIdx.x * GEMM_BM;

    // load A tile, split to tf32 hi/lo, store padded
    for (int i = tid; i < GEMM_BM * 32; i += 128) {
        int r = i >> 5, c = (i & 31) * 4;
        float4 v = make_float4(0.f, 0.f, 0.f, 0.f);
        if (block_row + r < M)
            v = *reinterpret_cast<const float4*>(A + (size_t)(block_row + r) * 128 + c);
        uint32_t h0 = f2tf32(v.x), h1 = f2tf32(v.y), h2 = f2tf32(v.z), h3 = f2tf32(v.w);
        uint32_t l0 = f2tf32(v.x - __uint_as_float(h0));
        uint32_t l1 = f2tf32(v.y - __uint_as_float(h1));
        uint32_t l2 = f2tf32(v.z - __uint_as_float(h2));
        uint32_t l3 = f2tf32(v.w - __uint_as_float(h3));
        *reinterpret_cast<uint4*>(&Ash[r * A_LDA + c]) = make_uint4(h0, h1, h2, h3);
        *reinterpret_cast<uint4*>(&Asl[r * A_LDA + c]) = make_uint4(l0, l1, l2, l3);
    }
    __syncthreads();

    const int wn = wid * 32;            // warp n base
    const int g  = lane >> 2;           // group id 0..7
    const int t  = lane & 3;            // thread-in-group

    float acc[2][4][4];
#pragma unroll
    for (int a = 0; a < 2; a++)
#pragma unroll
        for (int b = 0; b < 4; b++)
#pragma unroll
            for (int c = 0; c < 4; c++) acc[a][b][c] = 0.f;

#pragma unroll 2
    for (int ks = 0; ks < 16; ks++) {
        const int k0 = ks * 8;
        uint2 bh[4], bl[4];
#pragma unroll
        for (int nt = 0; nt < 4; nt++) {
            const int idx = (ks * 16 + (wn >> 3) + nt) * 32 + lane;
            bh[nt] = g_wfh[idx];
            bl[nt] = g_wfl[idx];
        }
        uint32_t ah[2][4], al[2][4];
#pragma unroll
        for (int mt = 0; mt < 2; mt++) {
            const int r0 = (mt * 16 + g) * A_LDA;
            ah[mt][0] = Ash[r0 + k0 + t];
            ah[mt][1] = Ash[r0 + 8 * A_LDA + k0 + t];
            ah[mt][2] = Ash[r0 + k0 + t + 4];
            ah[mt][3] = Ash[r0 + 8 * A_LDA + k0 + t + 4];
            al[mt][0] = Asl[r0 + k0 + t];
            al[mt][1] = Asl[r0 + 8 * A_LDA + k0 + t];
            al[mt][2] = Asl[r0 + k0 + t + 4];
            al[mt][3] = Asl[r0 + 8 * A_LDA + k0 + t + 4];
        }
#pragma unroll
        for (int mt = 0; mt < 2; mt++)
#pragma unroll
            for (int nt = 0; nt < 4; nt++) {
                MMA_TF32(acc[mt][nt], ah[mt], bh[nt]);   // hi*hi
                MMA_TF32(acc[mt][nt], ah[mt], bl[nt]);   // hi*lo
                MMA_TF32(acc[mt][nt], al[mt], bh[nt]);   // lo*hi
            }
    }

    // epilogue: c0/c1 -> (row, 2t..2t+1); c2/c3 -> (row+8, same)
    float* C = reinterpret_cast<float*>(g_bufA4);
#pragma unroll
    for (int mt = 0; mt < 2; mt++) {
        const int row0 = block_row + mt * 16 + g;
#pragma unroll
        for (int nt = 0; nt < 4; nt++) {
            const int col = wn + nt * 8 + t * 2;
            if (row0 < M)
                *reinterpret_cast<float2*>(C + (size_t)row0 * 128 + col) =
                    make_float2(acc[mt][nt][0], acc[mt][nt][1]);
            if (row0 + 8 < M)
                *reinterpret_cast<float2*>(C + (size_t)(row0 + 8) * 128 + col) =
                    make_float2(acc[mt][nt][2], acc[mt][nt][3]);
        }
    }
}
#define GEMM_SMEM (2 * GEMM_BM * A_LDA * 4)   // 33792 bytes

// ================= CSR build / aggregation / pool / fc (round-5 proven) =================
__global__ void zero_misc_kernel() {
    int i = blockIdx.x * blockDim.x + threadIdx.x;
    int stride = gridDim.x * blockDim.x;
    for (int k = i; k < NNODES; k += stride) g_cnti[k] = 0;
    if (i < NGRAPH * 128) g_pool[i] = 0.f;
    if (i < NGRAPH) g_gcnt[i] = 0.f;
}

__global__ void count_kernel(const int* __restrict__ dst, int E) {
    int e = blockIdx.x * blockDim.x + threadIdx.x;
    if (e >= E) return;
    atomicAdd(&g_cnti[dst[e]], 1);
}

__global__ __launch_bounds__(256)
void scanA_kernel() {
    __shared__ int ssum[8];
    const int tid = threadIdx.x;
    const int base = blockIdx.x * SCAN_CHUNK + tid * 4;
    int s = 0;
#pragma unroll
    for (int j = 0; j < 4; j++) {
        int idx = base + j;
        if (idx < NNODES) s += g_cnti[idx];
    }
#pragma unroll
    for (int o = 16; o > 0; o >>= 1) s += __shfl_down_sync(0xffffffffu, s, o);
    if ((tid & 31) == 0) ssum[tid >> 5] = s;
    __syncthreads();
    if (tid == 0) {
        int tt = 0;
#pragma unroll
        for (int w = 0; w < 8; w++) tt += ssum[w];
        g_bsum[blockIdx.x] = tt;
    }
}

__global__ __launch_bounds__(128)
void scanB_kernel() {
    __shared__ int sh[128];
    const int t = threadIdx.x;
    int v = (t < SCAN_NB) ? g_bsum[t] : 0;
    sh[t] = v;
    __syncthreads();
    for (int o = 1; o < 128; o <<= 1) {
        int add = (t >= o) ? sh[t - o] : 0;
        __syncthreads();
        sh[t] += add;
        __syncthreads();
    }
    if (t < SCAN_NB) g_bpre[t] = sh[t] - v;
    if (t == SCAN_NB - 1) g_off[NNODES] = sh[t];
}

__global__ __launch_bounds__(256)
void scanC_kernel() {
    __shared__ int warpsum[8];
    const int tid = threadIdx.x;
    const int lane = tid & 31;
    const int warp = tid >> 5;
    const int base = blockIdx.x * SCAN_CHUNK + tid * 4;

    int v[4];
    int t = 0;
#pragma unroll
    for (int j = 0; j < 4; j++) {
        int idx = base + j;
        v[j] = (idx < NNODES) ? g_cnti[idx] : 0;
        t += v[j];
    }
    int incl = t;
#pragma unroll
    for (int o = 1; o < 32; o <<= 1) {
        int n = __shfl_up_sync(0xffffffffu, incl, o);
        if (lane >= o) incl += n;
    }
    if (lane == 31) warpsum[warp] = incl;
    __syncthreads();
    if (tid == 0) {
        int run = 0;
#pragma unroll
        for (int w = 0; w < 8; w++) { int x = warpsum[w]; warpsum[w] = run; run += x; }
    }
    __syncthreads();
    int run = g_bpre[blockIdx.x] + warpsum[warp] + (incl - t);
#pragma unroll
    for (int j = 0; j < 4; j++) {
        int idx = base + j;
        if (idx < NNODES) {
            g_off[idx] = run;
            g_cursor[idx] = run;
            g_dinv[idx] = rsqrtf((float)v[j] + 1.0f);
            run += v[j];
        }
    }
}

__global__ void fill_kernel(const int* __restrict__ src,
                            const int* __restrict__ dst, int E) {
    int e = blockIdx.x * blockDim.x + threadIdx.x;
    if (e >= E) return;
    int d = dst[e];
    int pos = atomicAdd(&g_cursor[d], 1);
    g_elist[pos] = src[e];
}

__global__ __launch_bounds__(256)
void agg_gather_kernel(const float* __restrict__ bias) {
    const int node = (blockIdx.x * blockDim.x + threadIdx.x) >> 5;
    const int lane = threadIdx.x & 31;
    if (node >= NNODES) return;

    const float4* __restrict__ h4 = g_bufA4;
    const float dd = g_dinv[node];

    float4 hv = h4[(size_t)node * 32 + lane];
    const float ws = dd * dd;
    float4 acc;
    acc.x = ws * hv.x; acc.y = ws * hv.y; acc.z = ws * hv.z; acc.w = ws * hv.w;

    const int beg = g_off[node];
    const int end = g_off[node + 1];
    int i = beg;
    for (; i + 3 < end; i += 4) {
        int   s[4];
        float w[4];
        float4 v[4];
#pragma unroll
        for (int u = 0; u < 4; u++) s[u] = g_elist[i + u];
#pragma unroll
        for (int u = 0; u < 4; u++) w[u] = dd * g_dinv[s[u]];
#pragma unroll
        for (int u = 0; u < 4; u++) v[u] = h4[(size_t)s[u] * 32 + lane];
#pragma unroll
        for (int u = 0; u < 4; u++) {
            acc.x = fmaf(w[u], v[u].x, acc.x);
            acc.y = fmaf(w[u], v[u].y, acc.y);
            acc.z = fmaf(w[u], v[u].z, acc.z);
            acc.w = fmaf(w[u], v[u].w, acc.w);
        }
    }
    for (; i < end; i++) {
        const int s = g_elist[i];
        const float w = dd * g_dinv[s];
        const float4 v = h4[(size_t)s * 32 + lane];
        acc.x = fmaf(w, v.x, acc.x);
        acc.y = fmaf(w, v.y, acc.y);
        acc.z = fmaf(w, v.z, acc.z);
        acc.w = fmaf(w, v.w, acc.w);
    }

    const float4 bv = reinterpret_cast<const float4*>(bias)[lane];
    acc.x = fmaxf(acc.x + bv.x, 0.f);
    acc.y = fmaxf(acc.y + bv.y, 0.f);
    acc.z = fmaxf(acc.z + bv.z, 0.f);
    acc.w = fmaxf(acc.w + bv.w, 0.f);
    g_bufB4[(size_t)node * 32 + lane] = acc;
}

#define POOL_NODES_PER_BLOCK 128
__global__ __launch_bounds__(128)
void pool_kernel(const int* __restrict__ batch, int N) {
    const int n0 = blockIdx.x * POOL_NODES_PER_BLOCK;
    const int n1 = min(n0 + POOL_NODES_PER_BLOCK, N);
    const int d = threadIdx.x;
    const float* __restrict__ h = reinterpret_cast<const float*>(g_bufB4);

    float acc = 0.f, c = 0.f;
    int curg = -1;
    for (int n = n0; n < n1; n++) {
        const int g = batch[n];
        if (g != curg) {
            if (curg >= 0) {
                atomicAdd(&g_pool[curg * 128 + d], acc);
                if (d == 0) atomicAdd(&g_gcnt[curg], c);
            }
            curg = g; acc = 0.f; c = 0.f;
        }
        acc += h[(size_t)n * 128 + d];
        c += 1.f;
    }
    if (curg >= 0) {
        atomicAdd(&g_pool[curg * 128 + d], acc);
        if (d == 0) atomicAdd(&g_gcnt[curg], c);
    }
}

__global__ __launch_bounds__(128)
void fc_kernel(const float* __restrict__ W, const float* __restrict__ b,
               float* __restrict__ out) {
    __shared__ float row[128];
    const int g = blockIdx.x;
    const int j = threadIdx.x;
    const float inv = 1.0f / fmaxf(g_gcnt[g], 1.0f);
    row[j] = g_pool[g * 128 + j] * inv;
    __syncthreads();
    float acc = b[j];
#pragma unroll
    for (int k = 0; k < 128; k++)
        acc = fmaf(row[k], W[k * 128 + j], acc);
    out[g * 128 + j] = acc;
}

// ---------------- launch ----------------
extern "C" void kernel_launch(void* const* d_in, const int* in_sizes, int n_in,
                              void* d_out, int out_size) {
    const float* x   = (const float*)d_in[0];
    const int*   ei  = (const int*)d_in[1];    // int32 (JAX x64 disabled)
    const int*   bat = (const int*)d_in[2];
    const float* W1  = (const float*)d_in[3];
    const float* b1  = (const float*)d_in[4];
    const float* W2  = (const float*)d_in[5];
    const float* b2  = (const float*)d_in[6];
    const float* Wfc = (const float*)d_in[7];
    const float* bfc = (const float*)d_in[8];
    float*       out = (float*)d_out;

    const int N = in_sizes[2];
    const int E = in_sizes[1] / 2;
    const int* src = ei;
    const int* dst = ei + E;

    cudaFuncSetAttribute(tc_gemm_kernel, cudaFuncAttributeMaxDynamicSharedMemorySize, GEMM_SMEM);

    const int gemm_blocks = (N + GEMM_BM - 1) / GEMM_BM;   // 3125
    const int agg_blocks  = (N * 32 + 255) / 256;          // warp per node

    zero_misc_kernel<<<1184, 256>>>();                                  // 1
    count_kernel<<<(E + 255) / 256, 256>>>(dst, E);                     // 2
    wconv_kernel<<<32, 256>>>(W1);                                      // 3
    tc_gemm_kernel<<<gemm_blocks, 128, GEMM_SMEM>>>(x, 1, N);           // 4 <- profiled
    scanA_kernel<<<SCAN_NB, 256>>>();                                   // 5
    scanB_kernel<<<1, 128>>>();                                         // 6
    scanC_kernel<<<SCAN_NB, 256>>>();                                   // 7
    fill_kernel<<<(E + 255) / 256, 256>>>(src, dst, E);                 // 8
    agg_gather_kernel<<<agg_blocks, 256>>>(b1);                         // 9
    wconv_kernel<<<32, 256>>>(W2);                                      // 10
    tc_gemm_kernel<<<gemm_blocks, 128, GEMM_SMEM>>>(nullptr, 0, N);     // 11
    agg_gather_kernel<<<agg_blocks, 256>>>(b2);                         // 12
    pool_kernel<<<(N + POOL_NODES_PER_BLOCK - 1) / POOL_NODES_PER_BLOCK, 128>>>(bat, N); // 13
    fc_kernel<<<NGRAPH, 128>>>(Wfc, bfc, out);                          // 14
}

// round 10
// speedup vs baseline: 1.5687x; 1.1534x over previous
#include <cuda_runtime.h>
#include <cuda_bf16.h>
#include <cstdint>

// ---------------- problem constants ----------------
#define NNODES 100000
#define NEDGES 800000
#define NGRAPH 64
#define SCAN_CHUNK 1024
#define SCAN_NB ((NNODES + SCAN_CHUNK - 1) / SCAN_CHUNK)   // 98

// ---------------- scratch (static device globals; no allocation) ----------------
__device__ float4 g_bufA4[(size_t)NNODES * 32];   // 51.2 MB  (GEMM output h)
__device__ float4 g_bufB4[(size_t)NNODES * 32];   // 51.2 MB  (agg output / GEMM2 input)
__device__ float  g_dinv[NNODES];
__device__ int    g_cnti[NNODES];
__device__ int    g_off[NNODES + 1];
__device__ int    g_cursor[NNODES];
__device__ int    g_elist[NEDGES];
__device__ int    g_bsum[SCAN_NB];
__device__ int    g_bpre[SCAN_NB];
__device__ float  g_pool[NGRAPH * 128];
__device__ float  g_gcnt[NGRAPH];
// W fragments for mma.m16n8k16.bf16, pre-split hi/lo, fragment order:
// idx = (ks*16 + ntile)*32 + lane ; .x/.y = b0/b1 hi packs, .z/.w = b0/b1 lo packs
__device__ uint4  g_wfb[4096];   // 64 KB

// ---------------- bf16 split helpers ----------------
__device__ __forceinline__ void split2(float x, float y, uint32_t& hi, uint32_t& lo) {
    __nv_bfloat162 h = __floats2bfloat162_rn(x, y);
    float2 hf = __bfloat1622float2(h);
    __nv_bfloat162 l = __floats2bfloat162_rn(x - hf.x, y - hf.y);
    hi = *reinterpret_cast<uint32_t*>(&h);
    lo = *reinterpret_cast<uint32_t*>(&l);
}

#define MMA_BF16(d, a0, a1, a2, a3, b0, b1) \
    asm volatile("mma.sync.aligned.m16n8k16.row.col.f32.bf16.bf16.f32 " \
        "{%0,%1,%2,%3}, {%4,%5,%6,%7}, {%8,%9}, {%0,%1,%2,%3};" \
        : "+f"((d)[0]), "+f"((d)[1]), "+f"((d)[2]), "+f"((d)[3]) \
        : "r"(a0), "r"(a1), "r"(a2), "r"(a3), "r"(b0), "r"(b1))

// ---------------- W split-convert into fragment order ----------------
__global__ void wconv_kernel(const float* __restrict__ W) {
    int i = blockIdx.x * blockDim.x + threadIdx.x;
    if (i >= 4096) return;                 // (ks 0..7)(ntg 0..15)(lane 0..31)
    int lane = i & 31, ntg = (i >> 5) & 15, ks = i >> 9;
    int g = lane >> 2, t = lane & 3;
    int n = ntg * 8 + g;
    int k0 = ks * 16;
    float w0 = W[(size_t)(k0 + 2 * t)     * 128 + n];
    float w1 = W[(size_t)(k0 + 2 * t + 1) * 128 + n];
    float w2 = W[(size_t)(k0 + 2 * t + 8) * 128 + n];
    float w3 = W[(size_t)(k0 + 2 * t + 9) * 128 + n];
    uint32_t b0h, b0l, b1h, b1l;
    split2(w0, w1, b0h, b0l);
    split2(w2, w3, b1h, b1l);
    g_wfb[i] = make_uint4(b0h, b1h, b0l, b1l);
}

// ---------------- tensor-core GEMM (mma.sync m16n8k16, bf16x3 split) ----------------
// g_bufA = A[M,128] @ W[128,128]. CTA tile 32(m) x 128(n), 128 threads,
// 4 warps in 1x4 n-grid, warp tile 32x32.
// smem: A as interleaved (hi,lo) packed-bf16x2 uint2, [32][68] padded -> 17.4 KB.
#define LDA_P 68
#define GEMM_BM 32
__global__ __launch_bounds__(128)
void tc_gemm_kernel(const float* __restrict__ Aext, int useExt, int M) {
    extern __shared__ uint2 smA[];          // [32][LDA_P]: .x = hi pack, .y = lo pack
    const float* __restrict__ A = useExt ? Aext : reinterpret_cast<const float*>(g_bufB4);
    const int tid = threadIdx.x, lane = tid & 31, wid = tid >> 5;
    const int block_row = blockIdx.x * GEMM_BM;

    // load A tile (coalesced float4), split to packed bf16 hi/lo, store interleaved
    for (int i = tid; i < GEMM_BM * 32; i += 128) {
        int r = i >> 5, c4 = (i & 31) * 4;         // float col
        float4 v = make_float4(0.f, 0.f, 0.f, 0.f);
        if (block_row + r < M)
            v = *reinterpret_cast<const float4*>(A + (size_t)(block_row + r) * 128 + c4);
        uint32_t h01, l01, h23, l23;
        split2(v.x, v.y, h01, l01);
        split2(v.z, v.w, h23, l23);
        int kp = (i & 31) * 2;                     // bf16-pair col
        smA[r * LDA_P + kp]     = make_uint2(h01, l01);
        smA[r * LDA_P + kp + 1] = make_uint2(h23, l23);
    }
    __syncthreads();

    const int wn = wid * 32;            // warp n base
    const int g  = lane >> 2;
    const int t  = lane & 3;

    float acc[2][4][4];
#pragma unroll
    for (int a = 0; a < 2; a++)
#pragma unroll
        for (int b = 0; b < 4; b++)
#pragma unroll
            for (int c = 0; c < 4; c++) acc[a][b][c] = 0.f;

#pragma unroll
    for (int ks = 0; ks < 8; ks++) {
        const int k0p = ks * 8;                  // bf16-pair base col
        uint4 bf[4];
#pragma unroll
        for (int nt = 0; nt < 4; nt++)
            bf[nt] = g_wfb[((size_t)(ks * 16 + (wn >> 3) + nt) << 5) + lane];

#pragma unroll
        for (int mt = 0; mt < 2; mt++) {
            const int r0 = (mt * 16 + g) * LDA_P;
            const int r8 = r0 + 8 * LDA_P;
            uint2 q0 = smA[r0 + k0p + t];        // a0 (hi,lo)
            uint2 q1 = smA[r8 + k0p + t];        // a1
            uint2 q2 = smA[r0 + k0p + t + 4];    // a2
            uint2 q3 = smA[r8 + k0p + t + 4];    // a3
#pragma unroll
            for (int nt = 0; nt < 4; nt++) {
                MMA_BF16(acc[mt][nt], q0.x, q1.x, q2.x, q3.x, bf[nt].x, bf[nt].y); // hi*hi
                MMA_BF16(acc[mt][nt], q0.x, q1.x, q2.x, q3.x, bf[nt].z, bf[nt].w); // hi*lo
                MMA_BF16(acc[mt][nt], q0.y, q1.y, q2.y, q3.y, bf[nt].x, bf[nt].y); // lo*hi
            }
        }
    }

    // epilogue: c0/c1 -> (row, 2t..2t+1); c2/c3 -> (row+8, same)
    float* C = reinterpret_cast<float*>(g_bufA4);
#pragma unroll
    for (int mt = 0; mt < 2; mt++) {
        const int row0 = block_row + mt * 16 + g;
#pragma unroll
        for (int nt = 0; nt < 4; nt++) {
            const int col = wn + nt * 8 + t * 2;
            if (row0 < M)
                *reinterpret_cast<float2*>(C + (size_t)row0 * 128 + col) =
                    make_float2(acc[mt][nt][0], acc[mt][nt][1]);
            if (row0 + 8 < M)
                *reinterpret_cast<float2*>(C + (size_t)(row0 + 8) * 128 + col) =
                    make_float2(acc[mt][nt][2], acc[mt][nt][3]);
        }
    }
}
#define GEMM_SMEM (GEMM_BM * LDA_P * 8)   // 17408 bytes

// ================= CSR build / aggregation / pool / fc (round-9 proven) =================
__global__ void zero_misc_kernel() {
    int i = blockIdx.x * blockDim.x + threadIdx.x;
    int stride = gridDim.x * blockDim.x;
    for (int k = i; k < NNODES; k += stride) g_cnti[k] = 0;
    if (i < NGRAPH * 128) g_pool[i] = 0.f;
    if (i < NGRAPH) g_gcnt[i] = 0.f;
}

__global__ void count_kernel(const int* __restrict__ dst, int E) {
    int e = blockIdx.x * blockDim.x + threadIdx.x;
    if (e >= E) return;
    atomicAdd(&g_cnti[dst[e]], 1);
}

__global__ __launch_bounds__(256)
void scanA_kernel() {
    __shared__ int ssum[8];
    const int tid = threadIdx.x;
    const int base = blockIdx.x * SCAN_CHUNK + tid * 4;
    int s = 0;
#pragma unroll
    for (int j = 0; j < 4; j++) {
        int idx = base + j;
        if (idx < NNODES) s += g_cnti[idx];
    }
#pragma unroll
    for (int o = 16; o > 0; o >>= 1) s += __shfl_down_sync(0xffffffffu, s, o);
    if ((tid & 31) == 0) ssum[tid >> 5] = s;
    __syncthreads();
    if (tid == 0) {
        int tt = 0;
#pragma unroll
        for (int w = 0; w < 8; w++) tt += ssum[w];
        g_bsum[blockIdx.x] = tt;
    }
}

__global__ __launch_bounds__(128)
void scanB_kernel() {
    __shared__ int sh[128];
    const int t = threadIdx.x;
    int v = (t < SCAN_NB) ? g_bsum[t] : 0;
    sh[t] = v;
    __syncthreads();
    for (int o = 1; o < 128; o <<= 1) {
        int add = (t >= o) ? sh[t - o] : 0;
        __syncthreads();
        sh[t] += add;
        __syncthreads();
    }
    if (t < SCAN_NB) g_bpre[t] = sh[t] - v;
    if (t == SCAN_NB - 1) g_off[NNODES] = sh[t];
}

__global__ __launch_bounds__(256)
void scanC_kernel() {
    __shared__ int warpsum[8];
    const int tid = threadIdx.x;
    const int lane = tid & 31;
    const int warp = tid >> 5;
    const int base = blockIdx.x * SCAN_CHUNK + tid * 4;

    int v[4];
    int t = 0;
#pragma unroll
    for (int j = 0; j < 4; j++) {
        int idx = base + j;
        v[j] = (idx < NNODES) ? g_cnti[idx] : 0;
        t += v[j];
    }
    int incl = t;
#pragma unroll
    for (int o = 1; o < 32; o <<= 1) {
        int n = __shfl_up_sync(0xffffffffu, incl, o);
        if (lane >= o) incl += n;
    }
    if (lane == 31) warpsum[warp] = incl;
    __syncthreads();
    if (tid == 0) {
        int run = 0;
#pragma unroll
        for (int w = 0; w < 8; w++) { int x = warpsum[w]; warpsum[w] = run; run += x; }
    }
    __syncthreads();
    int run = g_bpre[blockIdx.x] + warpsum[warp] + (incl - t);
#pragma unroll
    for (int j = 0; j < 4; j++) {
        int idx = base + j;
        if (idx < NNODES) {
            g_off[idx] = run;
            g_cursor[idx] = run;
            g_dinv[idx] = rsqrtf((float)v[j] + 1.0f);
            run += v[j];
        }
    }
}

__global__ void fill_kernel(const int* __restrict__ src,
                            const int* __restrict__ dst, int E) {
    int e = blockIdx.x * blockDim.x + threadIdx.x;
    if (e >= E) return;
    int d = dst[e];
    int pos = atomicAdd(&g_cursor[d], 1);
    g_elist[pos] = src[e];
}

__global__ __launch_bounds__(256)
void agg_gather_kernel(const float* __restrict__ bias) {
    const int node = (blockIdx.x * blockDim.x + threadIdx.x) >> 5;
    const int lane = threadIdx.x & 31;
    if (node >= NNODES) return;

    const float4* __restrict__ h4 = g_bufA4;
    const float dd = g_dinv[node];

    float4 hv = h4[(size_t)node * 32 + lane];
    const float ws = dd * dd;
    float4 acc;
    acc.x = ws * hv.x; acc.y = ws * hv.y; acc.z = ws * hv.z; acc.w = ws * hv.w;

    const int beg = g_off[node];
    const int end = g_off[node + 1];
    int i = beg;
    for (; i + 3 < end; i += 4) {
        int   s[4];
        float w[4];
        float4 v[4];
#pragma unroll
        for (int u = 0; u < 4; u++) s[u] = g_elist[i + u];
#pragma unroll
        for (int u = 0; u < 4; u++) w[u] = dd * g_dinv[s[u]];
#pragma unroll
        for (int u = 0; u < 4; u++) v[u] = h4[(size_t)s[u] * 32 + lane];
#pragma unroll
        for (int u = 0; u < 4; u++) {
            acc.x = fmaf(w[u], v[u].x, acc.x);
            acc.y = fmaf(w[u], v[u].y, acc.y);
            acc.z = fmaf(w[u], v[u].z, acc.z);
            acc.w = fmaf(w[u], v[u].w, acc.w);
        }
    }
    for (; i < end; i++) {
        const int s = g_elist[i];
        const float w = dd * g_dinv[s];
        const float4 v = h4[(size_t)s * 32 + lane];
        acc.x = fmaf(w, v.x, acc.x);
        acc.y = fmaf(w, v.y, acc.y);
        acc.z = fmaf(w, v.z, acc.z);
        acc.w = fmaf(w, v.w, acc.w);
    }

    const float4 bv = reinterpret_cast<const float4*>(bias)[lane];
    acc.x = fmaxf(acc.x + bv.x, 0.f);
    acc.y = fmaxf(acc.y + bv.y, 0.f);
    acc.z = fmaxf(acc.z + bv.z, 0.f);
    acc.w = fmaxf(acc.w + bv.w, 0.f);
    g_bufB4[(size_t)node * 32 + lane] = acc;
}

#define POOL_NODES_PER_BLOCK 128
__global__ __launch_bounds__(128)
void pool_kernel(const int* __restrict__ batch, int N) {
    const int n0 = blockIdx.x * POOL_NODES_PER_BLOCK;
    const int n1 = min(n0 + POOL_NODES_PER_BLOCK, N);
    const int d = threadIdx.x;
    const float* __restrict__ h = reinterpret_cast<const float*>(g_bufB4);

    float acc = 0.f, c = 0.f;
    int curg = -1;
    for (int n = n0; n < n1; n++) {
        const int g = batch[n];
        if (g != curg) {
            if (curg >= 0) {
                atomicAdd(&g_pool[curg * 128 + d], acc);
                if (d == 0) atomicAdd(&g_gcnt[curg], c);
            }
            curg = g; acc = 0.f; c = 0.f;
        }
        acc += h[(size_t)n * 128 + d];
        c += 1.f;
    }
    if (curg >= 0) {
        atomicAdd(&g_pool[curg * 128 + d], acc);
        if (d == 0) atomicAdd(&g_gcnt[curg], c);
    }
}

__global__ __launch_bounds__(128)
void fc_kernel(const float* __restrict__ W, const float* __restrict__ b,
               float* __restrict__ out) {
    __shared__ float row[128];
    const int g = blockIdx.x;
    const int j = threadIdx.x;
    const float inv = 1.0f / fmaxf(g_gcnt[g], 1.0f);
    row[j] = g_pool[g * 128 + j] * inv;
    __syncthreads();
    float acc = b[j];
#pragma unroll
    for (int k = 0; k < 128; k++)
        acc = fmaf(row[k], W[k * 128 + j], acc);
    out[g * 128 + j] = acc;
}

// ---------------- launch ----------------
extern "C" void kernel_launch(void* const* d_in, const int* in_sizes, int n_in,
                              void* d_out, int out_size) {
    const float* x   = (const float*)d_in[0];
    const int*   ei  = (const int*)d_in[1];    // int32 (JAX x64 disabled)
    const int*   bat = (const int*)d_in[2];
    const float* W1  = (const float*)d_in[3];
    const float* b1  = (const float*)d_in[4];
    const float* W2  = (const float*)d_in[5];
    const float* b2  = (const float*)d_in[6];
    const float* Wfc = (const float*)d_in[7];
    const float* bfc = (const float*)d_in[8];
    float*       out = (float*)d_out;

    const int N = in_sizes[2];
    const int E = in_sizes[1] / 2;
    const int* src = ei;
    const int* dst = ei + E;

    cudaFuncSetAttribute(tc_gemm_kernel, cudaFuncAttributeMaxDynamicSharedMemorySize, GEMM_SMEM);

    const int gemm_blocks = (N + GEMM_BM - 1) / GEMM_BM;   // 3125
    const int agg_blocks  = (N * 32 + 255) / 256;          // warp per node

    zero_misc_kernel<<<1184, 256>>>();                                  // 1
    count_kernel<<<(E + 255) / 256, 256>>>(dst, E);                     // 2
    wconv_kernel<<<16, 256>>>(W1);                                      // 3
    tc_gemm_kernel<<<gemm_blocks, 128, GEMM_SMEM>>>(x, 1, N);           // 4 <- profiled
    scanA_kernel<<<SCAN_NB, 256>>>();                                   // 5
    scanB_kernel<<<1, 128>>>();                                         // 6
    scanC_kernel<<<SCAN_NB, 256>>>();                                   // 7
    fill_kernel<<<(E + 255) / 256, 256>>>(src, dst, E);                 // 8
    agg_gather_kernel<<<agg_blocks, 256>>>(b1);                         // 9
    wconv_kernel<<<16, 256>>>(W2);                                      // 10
    tc_gemm_kernel<<<gemm_blocks, 128, GEMM_SMEM>>>(nullptr, 0, N);     // 11
    agg_gather_kernel<<<agg_blocks, 256>>>(b2);                         // 12
    pool_kernel<<<(N + POOL_NODES_PER_BLOCK - 1) / POOL_NODES_PER_BLOCK, 128>>>(bat, N); // 13
    fc_kernel<<<NGRAPH, 128>>>(Wfc, bfc, out);                          // 14
}

// round 11
// speedup vs baseline: 1.6170x; 1.0308x over previous
#include <cuda_runtime.h>
#include <cuda_bf16.h>
#include <cstdint>

// ---------------- problem constants ----------------
#define NNODES 100000
#define NEDGES 800000
#define NGRAPH 64
#define SCAN_CHUNK 1024
#define SCAN_NB ((NNODES + SCAN_CHUNK - 1) / SCAN_CHUNK)   // 98

// ---------------- scratch (static device globals; no allocation) ----------------
__device__ float4 g_bufA4[(size_t)NNODES * 32];   // 51.2 MB  (GEMM output h)
__device__ float4 g_bufB4[(size_t)NNODES * 32];   // 51.2 MB  (agg output / GEMM2 input)
__device__ float  g_dinv[NNODES];
__device__ int    g_cnti[NNODES];
__device__ int    g_off[NNODES + 1];
__device__ int    g_cursor[NNODES];
__device__ int    g_elist[NEDGES];
__device__ int    g_bsum[SCAN_NB];
__device__ int    g_bpre[SCAN_NB];
__device__ float  g_pool[NGRAPH * 128];
__device__ float  g_gcnt[NGRAPH];
// W fragments for mma.m16n8k16.bf16, pre-split hi/lo, fragment order (2 layers):
// idx = (ks*16 + ntile)*32 + lane ; .x/.y = b0/b1 hi packs, .z/.w = b0/b1 lo packs
__device__ uint4  g_wfb[2][4096];   // 2 x 64 KB

// ---------------- bf16 split helpers ----------------
__device__ __forceinline__ void split2(float x, float y, uint32_t& hi, uint32_t& lo) {
    __nv_bfloat162 h = __floats2bfloat162_rn(x, y);
    float2 hf = __bfloat1622float2(h);
    __nv_bfloat162 l = __floats2bfloat162_rn(x - hf.x, y - hf.y);
    hi = *reinterpret_cast<uint32_t*>(&h);
    lo = *reinterpret_cast<uint32_t*>(&l);
}

#define MMA_BF16(d, a0, a1, a2, a3, b0, b1) \
    asm volatile("mma.sync.aligned.m16n8k16.row.col.f32.bf16.bf16.f32 " \
        "{%0,%1,%2,%3}, {%4,%5,%6,%7}, {%8,%9}, {%0,%1,%2,%3};" \
        : "+f"((d)[0]), "+f"((d)[1]), "+f"((d)[2]), "+f"((d)[3]) \
        : "r"(a0), "r"(a1), "r"(a2), "r"(a3), "r"(b0), "r"(b1))

// ---------------- W split-convert into fragment order ----------------
__global__ void wconv_kernel(const float* __restrict__ W, int sel) {
    int i = blockIdx.x * blockDim.x + threadIdx.x;
    if (i >= 4096) return;                 // (ks 0..7)(ntg 0..15)(lane 0..31)
    int lane = i & 31, ntg = (i >> 5) & 15, ks = i >> 9;
    int g = lane >> 2, t = lane & 3;
    int n = ntg * 8 + g;
    int k0 = ks * 16;
    float w0 = W[(size_t)(k0 + 2 * t)     * 128 + n];
    float w1 = W[(size_t)(k0 + 2 * t + 1) * 128 + n];
    float w2 = W[(size_t)(k0 + 2 * t + 8) * 128 + n];
    float w3 = W[(size_t)(k0 + 2 * t + 9) * 128 + n];
    uint32_t b0h, b0l, b1h, b1l;
    split2(w0, w1, b0h, b0l);
    split2(w2, w3, b1h, b1l);
    g_wfb[sel][i] = make_uint4(b0h, b1h, b0l, b1l);
}

// ---------------- tensor-core GEMM (mma.sync m16n8k16, bf16x3 split) ----------------
// g_bufA = A[M,128] @ W[128,128]. CTA tile 32(m) x 128(n), 256 threads,
// 8 warps in 1x8 n-grid, warp tile 32x16 (low-reg, high-occupancy).
// smem: A as interleaved (hi,lo) packed-bf16x2 uint2, [32][68] padded -> 17.4 KB.
#define LDA_P 68
#define GEMM_BM 32
__global__ __launch_bounds__(256)
void tc_gemm_kernel(const float* __restrict__ Aext, int useExt, int wsel, int M) {
    extern __shared__ uint2 smA[];          // [32][LDA_P]: .x = hi pack, .y = lo pack
    const float* __restrict__ A = useExt ? Aext : reinterpret_cast<const float*>(g_bufB4);
    const int tid = threadIdx.x, lane = tid & 31, wid = tid >> 5;
    const int block_row = blockIdx.x * GEMM_BM;

    // load A tile (coalesced float4), split to packed bf16 hi/lo, store interleaved
    for (int i = tid; i < GEMM_BM * 32; i += 256) {
        int r = i >> 5, c4 = (i & 31) * 4;         // float col
        float4 v = make_float4(0.f, 0.f, 0.f, 0.f);
        if (block_row + r < M)
            v = *reinterpret_cast<const float4*>(A + (size_t)(block_row + r) * 128 + c4);
        uint32_t h01, l01, h23, l23;
        split2(v.x, v.y, h01, l01);
        split2(v.z, v.w, h23, l23);
        int kp = (i & 31) * 2;                     // bf16-pair col
        smA[r * LDA_P + kp]     = make_uint2(h01, l01);
        smA[r * LDA_P + kp + 1] = make_uint2(h23, l23);
    }
    __syncthreads();

    const int wn = wid * 16;            // warp n base
    const int g  = lane >> 2;
    const int t  = lane & 3;
    const uint4* __restrict__ wf = g_wfb[wsel];

    float acc[2][2][4];
#pragma unroll
    for (int a = 0; a < 2; a++)
#pragma unroll
        for (int b = 0; b < 2; b++)
#pragma unroll
            for (int c = 0; c < 4; c++) acc[a][b][c] = 0.f;

#pragma unroll
    for (int ks = 0; ks < 8; ks++) {
        const int k0p = ks * 8;                  // bf16-pair base col
        uint4 bf[2];
#pragma unroll
        for (int nt = 0; nt < 2; nt++)
            bf[nt] = wf[((size_t)(ks * 16 + wid * 2 + nt) << 5) + lane];

#pragma unroll
        for (int mt = 0; mt < 2; mt++) {
            const int r0 = (mt * 16 + g) * LDA_P;
            const int r8 = r0 + 8 * LDA_P;
            uint2 q0 = smA[r0 + k0p + t];        // a0 (hi,lo)
            uint2 q1 = smA[r8 + k0p + t];        // a1
            uint2 q2 = smA[r0 + k0p + t + 4];    // a2
            uint2 q3 = smA[r8 + k0p + t + 4];    // a3
#pragma unroll
            for (int nt = 0; nt < 2; nt++) {
                MMA_BF16(acc[mt][nt], q0.x, q1.x, q2.x, q3.x, bf[nt].x, bf[nt].y); // hi*hi
                MMA_BF16(acc[mt][nt], q0.x, q1.x, q2.x, q3.x, bf[nt].z, bf[nt].w); // hi*lo
                MMA_BF16(acc[mt][nt], q0.y, q1.y, q2.y, q3.y, bf[nt].x, bf[nt].y); // lo*hi
            }
        }
    }

    // epilogue: c0/c1 -> (row, 2t..2t+1); c2/c3 -> (row+8, same)
    float* C = reinterpret_cast<float*>(g_bufA4);
#pragma unroll
    for (int mt = 0; mt < 2; mt++) {
        const int row0 = block_row + mt * 16 + g;
#pragma unroll
        for (int nt = 0; nt < 2; nt++) {
            const int col = wn + nt * 8 + t * 2;
            if (row0 < M)
                *reinterpret_cast<float2*>(C + (size_t)row0 * 128 + col) =
                    make_float2(acc[mt][nt][0], acc[mt][nt][1]);
            if (row0 + 8 < M)
                *reinterpret_cast<float2*>(C + (size_t)(row0 + 8) * 128 + col) =
                    make_float2(acc[mt][nt][2], acc[mt][nt][3]);
        }
    }
}
#define GEMM_SMEM (GEMM_BM * LDA_P * 8)   // 17408 bytes

// ================= CSR build / aggregation / pool / fc (round-10 proven) =================
__global__ void zero_misc_kernel() {
    int i = blockIdx.x * blockDim.x + threadIdx.x;
    int stride = gridDim.x * blockDim.x;
    for (int k = i; k < NNODES; k += stride) g_cnti[k] = 0;
    if (i < NGRAPH * 128) g_pool[i] = 0.f;
    if (i < NGRAPH) g_gcnt[i] = 0.f;
}

__global__ void count_kernel(const int* __restrict__ dst, int E) {
    int e = blockIdx.x * blockDim.x + threadIdx.x;
    if (e >= E) return;
    atomicAdd(&g_cnti[dst[e]], 1);
}

__global__ __launch_bounds__(256)
void scanA_kernel() {
    __shared__ int ssum[8];
    const int tid = threadIdx.x;
    const int base = blockIdx.x * SCAN_CHUNK + tid * 4;
    int s = 0;
#pragma unroll
    for (int j = 0; j < 4; j++) {
        int idx = base + j;
        if (idx < NNODES) s += g_cnti[idx];
    }
#pragma unroll
    for (int o = 16; o > 0; o >>= 1) s += __shfl_down_sync(0xffffffffu, s, o);
    if ((tid & 31) == 0) ssum[tid >> 5] = s;
    __syncthreads();
    if (tid == 0) {
        int tt = 0;
#pragma unroll
        for (int w = 0; w < 8; w++) tt += ssum[w];
        g_bsum[blockIdx.x] = tt;
    }
}

__global__ __launch_bounds__(128)
void scanB_kernel() {
    __shared__ int sh[128];
    const int t = threadIdx.x;
    int v = (t < SCAN_NB) ? g_bsum[t] : 0;
    sh[t] = v;
    __syncthreads();
    for (int o = 1; o < 128; o <<= 1) {
        int add = (t >= o) ? sh[t - o] : 0;
        __syncthreads();
        sh[t] += add;
        __syncthreads();
    }
    if (t < SCAN_NB) g_bpre[t] = sh[t] - v;
    if (t == SCAN_NB - 1) g_off[NNODES] = sh[t];
}

__global__ __launch_bounds__(256)
void scanC_kernel() {
    __shared__ int warpsum[8];
    const int tid = threadIdx.x;
    const int lane = tid & 31;
    const int warp = tid >> 5;
    const int base = blockIdx.x * SCAN_CHUNK + tid * 4;

    int v[4];
    int t = 0;
#pragma unroll
    for (int j = 0; j < 4; j++) {
        int idx = base + j;
        v[j] = (idx < NNODES) ? g_cnti[idx] : 0;
        t += v[j];
    }
    int incl = t;
#pragma unroll
    for (int o = 1; o < 32; o <<= 1) {
        int n = __shfl_up_sync(0xffffffffu, incl, o);
        if (lane >= o) incl += n;
    }
    if (lane == 31) warpsum[warp] = incl;
    __syncthreads();
    if (tid == 0) {
        int run = 0;
#pragma unroll
        for (int w = 0; w < 8; w++) { int x = warpsum[w]; warpsum[w] = run; run += x; }
    }
    __syncthreads();
    int run = g_bpre[blockIdx.x] + warpsum[warp] + (incl - t);
#pragma unroll
    for (int j = 0; j < 4; j++) {
        int idx = base + j;
        if (idx < NNODES) {
            g_off[idx] = run;
            g_cursor[idx] = run;
            g_dinv[idx] = rsqrtf((float)v[j] + 1.0f);
            run += v[j];
        }
    }
}

__global__ void fill_kernel(const int* __restrict__ src,
                            const int* __restrict__ dst, int E) {
    int e = blockIdx.x * blockDim.x + threadIdx.x;
    if (e >= E) return;
    int d = dst[e];
    int pos = atomicAdd(&g_cursor[d], 1);
    g_elist[pos] = src[e];
}

__global__ __launch_bounds__(256)
void agg_gather_kernel(const float* __restrict__ bias) {
    const int node = (blockIdx.x * blockDim.x + threadIdx.x) >> 5;
    const int lane = threadIdx.x & 31;
    if (node >= NNODES) return;

    const float4* __restrict__ h4 = g_bufA4;
    const float dd = g_dinv[node];

    float4 hv = h4[(size_t)node * 32 + lane];
    const float ws = dd * dd;
    float4 acc;
    acc.x = ws * hv.x; acc.y = ws * hv.y; acc.z = ws * hv.z; acc.w = ws * hv.w;

    const int beg = g_off[node];
    const int end = g_off[node + 1];
    int i = beg;
    for (; i + 3 < end; i += 4) {
        int   s[4];
        float w[4];
        float4 v[4];
#pragma unroll
        for (int u = 0; u < 4; u++) s[u] = g_elist[i + u];
#pragma unroll
        for (int u = 0; u < 4; u++) w[u] = dd * g_dinv[s[u]];
#pragma unroll
        for (int u = 0; u < 4; u++) v[u] = h4[(size_t)s[u] * 32 + lane];
#pragma unroll
        for (int u = 0; u < 4; u++) {
            acc.x = fmaf(w[u], v[u].x, acc.x);
            acc.y = fmaf(w[u], v[u].y, acc.y);
            acc.z = fmaf(w[u], v[u].z, acc.z);
            acc.w = fmaf(w[u], v[u].w, acc.w);
        }
    }
    for (; i < end; i++) {
        const int s = g_elist[i];
        const float w = dd * g_dinv[s];
        const float4 v = h4[(size_t)s * 32 + lane];
        acc.x = fmaf(w, v.x, acc.x);
        acc.y = fmaf(w, v.y, acc.y);
        acc.z = fmaf(w, v.z, acc.z);
        acc.w = fmaf(w, v.w, acc.w);
    }

    const float4 bv = reinterpret_cast<const float4*>(bias)[lane];
    acc.x = fmaxf(acc.x + bv.x, 0.f);
    acc.y = fmaxf(acc.y + bv.y, 0.f);
    acc.z = fmaxf(acc.z + bv.z, 0.f);
    acc.w = fmaxf(acc.w + bv.w, 0.f);
    g_bufB4[(size_t)node * 32 + lane] = acc;
}

#define POOL_NODES_PER_BLOCK 128
__global__ __launch_bounds__(128)
void pool_kernel(const int* __restrict__ batch, int N) {
    const int n0 = blockIdx.x * POOL_NODES_PER_BLOCK;
    const int n1 = min(n0 + POOL_NODES_PER_BLOCK, N);
    const int d = threadIdx.x;
    const float* __restrict__ h = reinterpret_cast<const float*>(g_bufB4);

    float acc = 0.f, c = 0.f;
    int curg = -1;
    for (int n = n0; n < n1; n++) {
        const int g = batch[n];
        if (g != curg) {
            if (curg >= 0) {
                atomicAdd(&g_pool[curg * 128 + d], acc);
                if (d == 0) atomicAdd(&g_gcnt[curg], c);
            }
            curg = g; acc = 0.f; c = 0.f;
        }
        acc += h[(size_t)n * 128 + d];
        c += 1.f;
    }
    if (curg >= 0) {
        atomicAdd(&g_pool[curg * 128 + d], acc);
        if (d == 0) atomicAdd(&g_gcnt[curg], c);
    }
}

__global__ __launch_bounds__(128)
void fc_kernel(const float* __restrict__ W, const float* __restrict__ b,
               float* __restrict__ out) {
    __shared__ float row[128];
    const int g = blockIdx.x;
    const int j = threadIdx.x;
    const float inv = 1.0f / fmaxf(g_gcnt[g], 1.0f);
    row[j] = g_pool[g * 128 + j] * inv;
    __syncthreads();
    float acc = b[j];
#pragma unroll
    for (int k = 0; k < 128; k++)
        acc = fmaf(row[k], W[k * 128 + j], acc);
    out[g * 128 + j] = acc;
}

// ---------------- launch ----------------
extern "C" void kernel_launch(void* const* d_in, const int* in_sizes, int n_in,
                              void* d_out, int out_size) {
    const float* x   = (const float*)d_in[0];
    const int*   ei  = (const int*)d_in[1];    // int32 (JAX x64 disabled)
    const int*   bat = (const int*)d_in[2];
    const float* W1  = (const float*)d_in[3];
    const float* b1  = (const float*)d_in[4];
    const float* W2  = (const float*)d_in[5];
    const float* b2  = (const float*)d_in[6];
    const float* Wfc = (const float*)d_in[7];
    const float* bfc = (const float*)d_in[8];
    float*       out = (float*)d_out;

    const int N = in_sizes[2];
    const int E = in_sizes[1] / 2;
    const int* src = ei;
    const int* dst = ei + E;

    // Streams/events created once on the FIRST (non-capture) call; reused
    // inside capture as fork/join nodes. No device allocation involved.
    static cudaStream_t s_gemm = nullptr;
    static cudaEvent_t  ev_fork = nullptr, ev_gemm1 = nullptr;
    if (!s_gemm) {
        cudaStreamCreateWithFlags(&s_gemm, cudaStreamNonBlocking);
        cudaEventCreateWithFlags(&ev_fork, cudaEventDisableTiming);
        cudaEventCreateWithFlags(&ev_gemm1, cudaEventDisableTiming);
    }

    cudaFuncSetAttribute(tc_gemm_kernel, cudaFuncAttributeMaxDynamicSharedMemorySize, GEMM_SMEM);

    const int gemm_blocks = (N + GEMM_BM - 1) / GEMM_BM;   // 3125
    const int agg_blocks  = (N * 32 + 255) / 256;          // warp per node

    // --- fork: GEMM branch runs concurrently with the CSR build ---
    cudaEventRecord(ev_fork, 0);
    cudaStreamWaitEvent(s_gemm, ev_fork, 0);
    wconv_kernel<<<16, 256, 0, s_gemm>>>(W1, 0);
    wconv_kernel<<<16, 256, 0, s_gemm>>>(W2, 1);
    tc_gemm_kernel<<<gemm_blocks, 256, GEMM_SMEM, s_gemm>>>(x, 1, 0, N);
    cudaEventRecord(ev_gemm1, s_gemm);

    // --- default stream: CSR build ---
    zero_misc_kernel<<<1184, 256>>>();
    count_kernel<<<(E + 255) / 256, 256>>>(dst, E);
    scanA_kernel<<<SCAN_NB, 256>>>();
    scanB_kernel<<<1, 128>>>();
    scanC_kernel<<<SCAN_NB, 256>>>();
    fill_kernel<<<(E + 255) / 256, 256>>>(src, dst, E);

    // --- join, then the dependent chain ---
    cudaStreamWaitEvent(0, ev_gemm1, 0);
    agg_gather_kernel<<<agg_blocks, 256>>>(b1);
    tc_gemm_kernel<<<gemm_blocks, 256, GEMM_SMEM>>>(nullptr, 0, 1, N);
    agg_gather_kernel<<<agg_blocks, 256>>>(b2);
    pool_kernel<<<(N + POOL_NODES_PER_BLOCK - 1) / POOL_NODES_PER_BLOCK, 128>>>(bat, N);
    fc_kernel<<<NGRAPH, 128>>>(Wfc, bfc, out);
}

// round 12
// speedup vs baseline: 1.9299x; 1.1935x over previous
#include <cuda_runtime.h>
#include <cuda_bf16.h>
#include <cstdint>

// ---------------- problem constants ----------------
#define NNODES 100000
#define NEDGES 800000
#define NGRAPH 64
#define SCAN_CHUNK 1024
#define SCAN_NB ((NNODES + SCAN_CHUNK - 1) / SCAN_CHUNK)   // 98

// ---------------- scratch (static device globals; no allocation) ----------------
__device__ float4 g_bufA4[(size_t)NNODES * 32];   // 51.2 MB  (GEMM output h)
__device__ float4 g_bufB4[(size_t)NNODES * 32];   // 51.2 MB  (agg1 output / GEMM2 input)
__device__ float  g_dinv[NNODES];
__device__ int    g_cnti[NNODES];
__device__ int    g_off[NNODES + 1];
__device__ int    g_cursor[NNODES];
__device__ int    g_elist[NEDGES];
__device__ int    g_bsum[SCAN_NB];
__device__ int    g_bpre[SCAN_NB];
__device__ float  g_pool[NGRAPH * 128];
__device__ float  g_gcnt[NGRAPH];
// W fragments for mma.m16n8k16.bf16, pre-split hi/lo, fragment order (2 layers)
__device__ uint4  g_wfb[2][4096];   // 2 x 64 KB

// ---------------- bf16 split helpers ----------------
__device__ __forceinline__ void split2(float x, float y, uint32_t& hi, uint32_t& lo) {
    __nv_bfloat162 h = __floats2bfloat162_rn(x, y);
    float2 hf = __bfloat1622float2(h);
    __nv_bfloat162 l = __floats2bfloat162_rn(x - hf.x, y - hf.y);
    hi = *reinterpret_cast<uint32_t*>(&h);
    lo = *reinterpret_cast<uint32_t*>(&l);
}

#define MMA_BF16(d, a0, a1, a2, a3, b0, b1) \
    asm volatile("mma.sync.aligned.m16n8k16.row.col.f32.bf16.bf16.f32 " \
        "{%0,%1,%2,%3}, {%4,%5,%6,%7}, {%8,%9}, {%0,%1,%2,%3};" \
        : "+f"((d)[0]), "+f"((d)[1]), "+f"((d)[2]), "+f"((d)[3]) \
        : "r"(a0), "r"(a1), "r"(a2), "r"(a3), "r"(b0), "r"(b1))

// ---------------- W split-convert into fragment order ----------------
__global__ void wconv_kernel(const float* __restrict__ W, int sel) {
    int i = blockIdx.x * blockDim.x + threadIdx.x;
    if (i >= 4096) return;
    int lane = i & 31, ntg = (i >> 5) & 15, ks = i >> 9;
    int g = lane >> 2, t = lane & 3;
    int n = ntg * 8 + g;
    int k0 = ks * 16;
    float w0 = W[(size_t)(k0 + 2 * t)     * 128 + n];
    float w1 = W[(size_t)(k0 + 2 * t + 1) * 128 + n];
    float w2 = W[(size_t)(k0 + 2 * t + 8) * 128 + n];
    float w3 = W[(size_t)(k0 + 2 * t + 9) * 128 + n];
    uint32_t b0h, b0l, b1h, b1l;
    split2(w0, w1, b0h, b0l);
    split2(w2, w3, b1h, b1l);
    g_wfb[sel][i] = make_uint4(b0h, b1h, b0l, b1l);
}

// ---------------- tensor-core GEMM (mma.sync m16n8k16, bf16x3 split) ----------------
// g_bufA = A[M,128] @ W[128,128]. CTA 32(m) x 128(n), 256 threads, 8 warps 1x8, warp tile 32x16.
#define LDA_P 68
#define GEMM_BM 32
__global__ __launch_bounds__(256)
void tc_gemm_kernel(const float* __restrict__ Aext, int useExt, int wsel, int M) {
    extern __shared__ uint2 smA[];          // [32][LDA_P]: .x = hi pack, .y = lo pack
    const float* __restrict__ A = useExt ? Aext : reinterpret_cast<const float*>(g_bufB4);
    const int tid = threadIdx.x, lane = tid & 31, wid = tid >> 5;
    const int block_row = blockIdx.x * GEMM_BM;

    for (int i = tid; i < GEMM_BM * 32; i += 256) {
        int r = i >> 5, c4 = (i & 31) * 4;
        float4 v = make_float4(0.f, 0.f, 0.f, 0.f);
        if (block_row + r < M)
            v = *reinterpret_cast<const float4*>(A + (size_t)(block_row + r) * 128 + c4);
        uint32_t h01, l01, h23, l23;
        split2(v.x, v.y, h01, l01);
        split2(v.z, v.w, h23, l23);
        int kp = (i & 31) * 2;
        smA[r * LDA_P + kp]     = make_uint2(h01, l01);
        smA[r * LDA_P + kp + 1] = make_uint2(h23, l23);
    }
    __syncthreads();

    const int wn = wid * 16;
    const int g  = lane >> 2;
    const int t  = lane & 3;
    const uint4* __restrict__ wf = g_wfb[wsel];

    float acc[2][2][4];
#pragma unroll
    for (int a = 0; a < 2; a++)
#pragma unroll
        for (int b = 0; b < 2; b++)
#pragma unroll
            for (int c = 0; c < 4; c++) acc[a][b][c] = 0.f;

#pragma unroll
    for (int ks = 0; ks < 8; ks++) {
        const int k0p = ks * 8;
        uint4 bf[2];
#pragma unroll
        for (int nt = 0; nt < 2; nt++)
            bf[nt] = wf[((size_t)(ks * 16 + wid * 2 + nt) << 5) + lane];

#pragma unroll
        for (int mt = 0; mt < 2; mt++) {
            const int r0 = (mt * 16 + g) * LDA_P;
            const int r8 = r0 + 8 * LDA_P;
            uint2 q0 = smA[r0 + k0p + t];
            uint2 q1 = smA[r8 + k0p + t];
            uint2 q2 = smA[r0 + k0p + t + 4];
            uint2 q3 = smA[r8 + k0p + t + 4];
#pragma unroll
            for (int nt = 0; nt < 2; nt++) {
                MMA_BF16(acc[mt][nt], q0.x, q1.x, q2.x, q3.x, bf[nt].x, bf[nt].y);
                MMA_BF16(acc[mt][nt], q0.x, q1.x, q2.x, q3.x, bf[nt].z, bf[nt].w);
                MMA_BF16(acc[mt][nt], q0.y, q1.y, q2.y, q3.y, bf[nt].x, bf[nt].y);
            }
        }
    }

    float* C = reinterpret_cast<float*>(g_bufA4);
#pragma unroll
    for (int mt = 0; mt < 2; mt++) {
        const int row0 = block_row + mt * 16 + g;
#pragma unroll
        for (int nt = 0; nt < 2; nt++) {
            const int col = wn + nt * 8 + t * 2;
            if (row0 < M)
                *reinterpret_cast<float2*>(C + (size_t)row0 * 128 + col) =
                    make_float2(acc[mt][nt][0], acc[mt][nt][1]);
            if (row0 + 8 < M)
                *reinterpret_cast<float2*>(C + (size_t)(row0 + 8) * 128 + col) =
                    make_float2(acc[mt][nt][2], acc[mt][nt][3]);
        }
    }
}
#define GEMM_SMEM (GEMM_BM * LDA_P * 8)   // 17408 bytes

// ================= CSR build =================
__global__ void zero_misc_kernel() {
    int i = blockIdx.x * blockDim.x + threadIdx.x;
    int stride = gridDim.x * blockDim.x;
    for (int k = i; k < NNODES; k += stride) g_cnti[k] = 0;
    if (i < NGRAPH * 128) g_pool[i] = 0.f;
}

__global__ void count_kernel(const int* __restrict__ dst, int E) {
    int e = blockIdx.x * blockDim.x + threadIdx.x;
    if (e >= E) return;
    atomicAdd(&g_cnti[dst[e]], 1);
}

// counts per graph via binary search on sorted batch ids
__global__ void gcnt_kernel(const int* __restrict__ batch, int N) {
    int g = threadIdx.x;
    if (g >= NGRAPH) return;
    // lower_bound(g) and lower_bound(g+1)
    int lo = 0, hi = N;
    while (lo < hi) { int m = (lo + hi) >> 1; if (batch[m] < g) lo = m + 1; else hi = m; }
    int b0 = lo;
    lo = 0; hi = N;
    while (lo < hi) { int m = (lo + hi) >> 1; if (batch[m] < g + 1) lo = m + 1; else hi = m; }
    g_gcnt[g] = (float)(lo - b0);
}

__global__ __launch_bounds__(256)
void scanA_kernel() {
    __shared__ int ssum[8];
    const int tid = threadIdx.x;
    const int base = blockIdx.x * SCAN_CHUNK + tid * 4;
    int s = 0;
#pragma unroll
    for (int j = 0; j < 4; j++) {
        int idx = base + j;
        if (idx < NNODES) s += g_cnti[idx];
    }
#pragma unroll
    for (int o = 16; o > 0; o >>= 1) s += __shfl_down_sync(0xffffffffu, s, o);
    if ((tid & 31) == 0) ssum[tid >> 5] = s;
    __syncthreads();
    if (tid == 0) {
        int tt = 0;
#pragma unroll
        for (int w = 0; w < 8; w++) tt += ssum[w];
        g_bsum[blockIdx.x] = tt;
    }
}

__global__ __launch_bounds__(128)
void scanB_kernel() {
    __shared__ int sh[128];
    const int t = threadIdx.x;
    int v = (t < SCAN_NB) ? g_bsum[t] : 0;
    sh[t] = v;
    __syncthreads();
    for (int o = 1; o < 128; o <<= 1) {
        int add = (t >= o) ? sh[t - o] : 0;
        __syncthreads();
        sh[t] += add;
        __syncthreads();
    }
    if (t < SCAN_NB) g_bpre[t] = sh[t] - v;
    if (t == SCAN_NB - 1) g_off[NNODES] = sh[t];
}

__global__ __launch_bounds__(256)
void scanC_kernel() {
    __shared__ int warpsum[8];
    const int tid = threadIdx.x;
    const int lane = tid & 31;
    const int warp = tid >> 5;
    const int base = blockIdx.x * SCAN_CHUNK + tid * 4;

    int v[4];
    int t = 0;
#pragma unroll
    for (int j = 0; j < 4; j++) {
        int idx = base + j;
        v[j] = (idx < NNODES) ? g_cnti[idx] : 0;
        t += v[j];
    }
    int incl = t;
#pragma unroll
    for (int o = 1; o < 32; o <<= 1) {
        int n = __shfl_up_sync(0xffffffffu, incl, o);
        if (lane >= o) incl += n;
    }
    if (lane == 31) warpsum[warp] = incl;
    __syncthreads();
    if (tid == 0) {
        int run = 0;
#pragma unroll
        for (int w = 0; w < 8; w++) { int x = warpsum[w]; warpsum[w] = run; run += x; }
    }
    __syncthreads();
    int run = g_bpre[blockIdx.x] + warpsum[warp] + (incl - t);
#pragma unroll
    for (int j = 0; j < 4; j++) {
        int idx = base + j;
        if (idx < NNODES) {
            g_off[idx] = run;
            g_cursor[idx] = run;
            g_dinv[idx] = rsqrtf((float)v[j] + 1.0f);
            run += v[j];
        }
    }
}

__global__ void fill_kernel(const int* __restrict__ src,
                            const int* __restrict__ dst, int E) {
    int e = blockIdx.x * blockDim.x + threadIdx.x;
    if (e >= E) return;
    int d = dst[e];
    int pos = atomicAdd(&g_cursor[d], 1);
    g_elist[pos] = src[e];
}

// ---------------- shared inner: gather + self-loop + bias + relu -> acc ----------------
__device__ __forceinline__ float4 agg_row(int node, int lane, const float4* __restrict__ h4,
                                          const float* __restrict__ bias) {
    const float dd = g_dinv[node];
    float4 hv = h4[(size_t)node * 32 + lane];
    const float ws = dd * dd;
    float4 acc;
    acc.x = ws * hv.x; acc.y = ws * hv.y; acc.z = ws * hv.z; acc.w = ws * hv.w;

    const int beg = g_off[node];
    const int end = g_off[node + 1];
    int i = beg;
    for (; i + 3 < end; i += 4) {
        int   s[4];
        float w[4];
        float4 v[4];
#pragma unroll
        for (int u = 0; u < 4; u++) s[u] = g_elist[i + u];
#pragma unroll
        for (int u = 0; u < 4; u++) w[u] = dd * g_dinv[s[u]];
#pragma unroll
        for (int u = 0; u < 4; u++) v[u] = h4[(size_t)s[u] * 32 + lane];
#pragma unroll
        for (int u = 0; u < 4; u++) {
            acc.x = fmaf(w[u], v[u].x, acc.x);
            acc.y = fmaf(w[u], v[u].y, acc.y);
            acc.z = fmaf(w[u], v[u].z, acc.z);
            acc.w = fmaf(w[u], v[u].w, acc.w);
        }
    }
    for (; i < end; i++) {
        const int s = g_elist[i];
        const float w = dd * g_dinv[s];
        const float4 v = h4[(size_t)s * 32 + lane];
        acc.x = fmaf(w, v.x, acc.x);
        acc.y = fmaf(w, v.y, acc.y);
        acc.z = fmaf(w, v.z, acc.z);
        acc.w = fmaf(w, v.w, acc.w);
    }

    const float4 bv = reinterpret_cast<const float4*>(bias)[lane];
    acc.x = fmaxf(acc.x + bv.x, 0.f);
    acc.y = fmaxf(acc.y + bv.y, 0.f);
    acc.z = fmaxf(acc.z + bv.z, 0.f);
    acc.w = fmaxf(acc.w + bv.w, 0.f);
    return acc;
}

// ---------------- layer-1 aggregation: writes h1 to bufB ----------------
__global__ __launch_bounds__(256)
void agg_gather_kernel(const float* __restrict__ bias) {
    const int node = (blockIdx.x * blockDim.x + threadIdx.x) >> 5;
    const int lane = threadIdx.x & 31;
    if (node >= NNODES) return;
    g_bufB4[(size_t)node * 32 + lane] = agg_row(node, lane, g_bufA4, bias);
}

// ---------------- layer-2 aggregation FUSED with mean-pool accumulation ----------------
// 8 warps = 8 contiguous nodes per block; rows staged in smem, block-level
// segmented reduction over (sorted) graph ids, one atomicAdd row per run.
__global__ __launch_bounds__(256)
void agg_pool_kernel(const float* __restrict__ bias, const int* __restrict__ batch, int N) {
    __shared__ float sbuf[8][128];
    __shared__ int   sgid[8];
    const int tid  = threadIdx.x;
    const int wid  = tid >> 5;
    const int lane = tid & 31;
    const int node = blockIdx.x * 8 + wid;

    if (node < N) {
        float4 acc = agg_row(node, lane, g_bufA4, bias);
        *reinterpret_cast<float4*>(&sbuf[wid][lane * 4]) = acc;
        if (lane == 0) sgid[wid] = batch[node];
    } else if (lane == 0) {
        sgid[wid] = -1;
    }
    __syncthreads();

    if (tid < 128) {
        const int d = tid;
        int curg = -1;
        float run = 0.f;
#pragma unroll
        for (int w = 0; w < 8; w++) {
            const int g = sgid[w];
            if (g < 0) break;               // tail block: remaining warps invalid
            if (g != curg) {
                if (curg >= 0) atomicAdd(&g_pool[curg * 128 + d], run);
                curg = g; run = 0.f;
            }
            run += sbuf[w][d];
        }
        if (curg >= 0) atomicAdd(&g_pool[curg * 128 + d], run);
    }
}

// ---------------- FC head ----------------
__global__ __launch_bounds__(128)
void fc_kernel(const float* __restrict__ W, const float* __restrict__ b,
               float* __restrict__ out) {
    __shared__ float row[128];
    const int g = blockIdx.x;
    const int j = threadIdx.x;
    const float inv = 1.0f / fmaxf(g_gcnt[g], 1.0f);
    row[j] = g_pool[g * 128 + j] * inv;
    __syncthreads();
    float acc = b[j];
#pragma unroll
    for (int k = 0; k < 128; k++)
        acc = fmaf(row[k], W[k * 128 + j], acc);
    out[g * 128 + j] = acc;
}

// ---------------- launch ----------------
extern "C" void kernel_launch(void* const* d_in, const int* in_sizes, int n_in,
                              void* d_out, int out_size) {
    const float* x   = (const float*)d_in[0];
    const int*   ei  = (const int*)d_in[1];    // int32 (JAX x64 disabled)
    const int*   bat = (const int*)d_in[2];
    const float* W1  = (const float*)d_in[3];
    const float* b1  = (const float*)d_in[4];
    const float* W2  = (const float*)d_in[5];
    const float* b2  = (const float*)d_in[6];
    const float* Wfc = (const float*)d_in[7];
    const float* bfc = (const float*)d_in[8];
    float*       out = (float*)d_out;

    const int N = in_sizes[2];
    const int E = in_sizes[1] / 2;
    const int* src = ei;
    const int* dst = ei + E;

    static cudaStream_t s_gemm = nullptr;
    static cudaEvent_t  ev_fork = nullptr, ev_gemm1 = nullptr;
    if (!s_gemm) {
        cudaStreamCreateWithFlags(&s_gemm, cudaStreamNonBlocking);
        cudaEventCreateWithFlags(&ev_fork, cudaEventDisableTiming);
        cudaEventCreateWithFlags(&ev_gemm1, cudaEventDisableTiming);
    }

    cudaFuncSetAttribute(tc_gemm_kernel, cudaFuncAttributeMaxDynamicSharedMemorySize, GEMM_SMEM);

    const int gemm_blocks = (N + GEMM_BM - 1) / GEMM_BM;   // 3125
    const int agg_blocks  = (N * 32 + 255) / 256;          // warp per node

    // --- fork: GEMM branch runs concurrently with the CSR build ---
    cudaEventRecord(ev_fork, 0);
    cudaStreamWaitEvent(s_gemm, ev_fork, 0);
    wconv_kernel<<<16, 256, 0, s_gemm>>>(W1, 0);
    wconv_kernel<<<16, 256, 0, s_gemm>>>(W2, 1);
    tc_gemm_kernel<<<gemm_blocks, 256, GEMM_SMEM, s_gemm>>>(x, 1, 0, N);
    cudaEventRecord(ev_gemm1, s_gemm);

    // --- default stream: CSR build + graph counts ---
    zero_misc_kernel<<<1184, 256>>>();
    count_kernel<<<(E + 255) / 256, 256>>>(dst, E);
    gcnt_kernel<<<1, NGRAPH>>>(bat, N);
    scanA_kernel<<<SCAN_NB, 256>>>();
    scanB_kernel<<<1, 128>>>();
    scanC_kernel<<<SCAN_NB, 256>>>();
    fill_kernel<<<(E + 255) / 256, 256>>>(src, dst, E);

    // --- join, then the dependent chain ---
    cudaStreamWaitEvent(0, ev_gemm1, 0);
    agg_gather_kernel<<<agg_blocks, 256>>>(b1);
    tc_gemm_kernel<<<gemm_blocks, 256, GEMM_SMEM>>>(nullptr, 0, 1, N);
    agg_pool_kernel<<<(N + 7) / 8, 256>>>(b2, bat, N);
    fc_kernel<<<NGRAPH, 128>>>(Wfc, bfc, out);
}